// round 2
// baseline (speedup 1.0000x reference)
#include <cuda_runtime.h>
#include <cstdint>
#include <math.h>

// Problem constants
#define S_LEN  128
#define BATCH  128
#define EDIM   64
#define HDIM   8
#define NQW    8      // quantum wires in head == HDIM
#define NQ     8      // qubits in QGate
#define TDIM   12
#define NROWS  (S_LEN*BATCH)   // 16384
#define FULLM  0xffffffffu

// -------------------- device scratch (no allocations allowed) ---------------
__device__ float g_Zx[NROWS * 32];    // per-(s,b) input projection (+b_in+phi), 2 MB
__device__ float g_hs[NROWS * HDIM];  // hidden states hs[s][b][h], 512 KB
__device__ int   g_flag;              // 1 => sentence buffer is int32, 0 => int64

// ============================================================================
// Host-side: numpy-legacy MT19937 reproduction for _build_random_layer(seed=1234)
// ============================================================================
namespace mtrng {
struct MT { uint32_t key[624]; int pos; };
static void mt_seed(MT& st, uint32_t s) {
    for (int i = 0; i < 624; i++) { st.key[i] = s; s = 1812433253u * (s ^ (s >> 30)) + (uint32_t)i + 1u; }
    st.pos = 624;
}
static void mt_gen(MT& st) {
    int i; uint32_t y;
    for (i = 0; i < 624 - 397; i++) {
        y = (st.key[i] & 0x80000000u) | (st.key[i + 1] & 0x7fffffffu);
        st.key[i] = st.key[i + 397] ^ (y >> 1) ^ ((y & 1u) ? 0x9908b0dfu : 0u);
    }
    for (; i < 623; i++) {
        y = (st.key[i] & 0x80000000u) | (st.key[i + 1] & 0x7fffffffu);
        st.key[i] = st.key[i - 227] ^ (y >> 1) ^ ((y & 1u) ? 0x9908b0dfu : 0u);
    }
    y = (st.key[623] & 0x80000000u) | (st.key[0] & 0x7fffffffu);
    st.key[623] = st.key[396] ^ (y >> 1) ^ ((y & 1u) ? 0x9908b0dfu : 0u);
    st.pos = 0;
}
static uint32_t mt_next(MT& st) {
    if (st.pos == 624) mt_gen(st);
    uint32_t y = st.key[st.pos++];
    y ^= y >> 11; y ^= (y << 7) & 0x9d2c5680u; y ^= (y << 15) & 0xefc60000u; y ^= y >> 18;
    return y;
}
// numpy legacy randint(0, n): masked rejection on ONE 32-bit draw (range < 2^32)
static int mt_randint(MT& st, uint32_t n) {
    uint32_t rng = n - 1u;
    uint32_t mask = rng;
    mask |= mask >> 1; mask |= mask >> 2; mask |= mask >> 4; mask |= mask >> 8; mask |= mask >> 16;
    uint32_t v;
    do { v = mt_next(st) & mask; } while (v > rng);
    return (int)v;
}
// numpy next_double: two 32-bit draws -> 53-bit double in [0,1)
static double mt_double(MT& st) {
    uint32_t a = mt_next(st) >> 5, b = mt_next(st) >> 6;
    return ((double)a * 67108864.0 + (double)b) / 9007199254740992.0;
}
} // namespace mtrng

struct OpsParam {
    int   type[32];  // 0 rx, 1 ry, 2 rz, 3 cnot
    int   pa[32];    // wire / control
    int   pb[32];    // target (cnot)
    float c[32], s[32];  // cos(theta/2), sin(theta/2)
    int   n;
};

static void build_ops(OpsParam& P) {
    mtrng::MT st; mtrng::mt_seed(st, 1234u);
    int n = 0;
    for (int i = 0; i < 30; i++) {
        int kind = mtrng::mt_randint(st, 4);
        if (kind == 3) {
            int c = mtrng::mt_randint(st, 8);
            int t = mtrng::mt_randint(st, 7);
            if (t >= c) t += 1;
            P.type[n] = 3; P.pa[n] = c; P.pb[n] = t; P.c[n] = 0.f; P.s[n] = 0.f; n++;
        } else {
            int g = kind % 3;                 // 0 rx, 1 ry, 2 rz
            int w = mtrng::mt_randint(st, 8);
            double ang = mtrng::mt_double(st) * (2.0 * M_PI);
            float th = (float)ang;            // reference casts to float32
            double half = (double)(th * 0.5f);
            P.type[n] = g; P.pa[n] = w; P.pb[n] = -1;
            P.c[n] = (float)cos(half); P.s[n] = (float)sin(half); n++;
        }
    }
    P.n = n;
}

// ============================================================================
// Kernel A: detect sentence dtype (int64 vs int32) without host readback
// ============================================================================
__global__ void k_detect(const int* __restrict__ sent32) {
    __shared__ int any;
    if (threadIdx.x == 0) any = 0;
    __syncthreads();
    int loc = 0;
    for (int i = threadIdx.x; i < 8192; i += blockDim.x)
        loc |= sent32[2 * i + 1];   // high words if int64 (all zero), real tokens if int32
    if (loc) atomicOr(&any, 1);
    __syncthreads();
    if (threadIdx.x == 0) g_flag = any ? 1 : 0;   // 1 => int32 data
}

// ============================================================================
// Kernel B: embed-gather + input projection  Zx[s][b][32] = Win_x·x + b_in + phi
// One warp per (s,b) row. 16384 warps.
// ============================================================================
__global__ void k_project(const float* __restrict__ emb,
                          const float* __restrict__ Win,
                          const float* __restrict__ b_in,
                          const float* __restrict__ phi,
                          const int*   __restrict__ sent32) {
    int warp = blockIdx.x * (blockDim.x >> 5) + (threadIdx.x >> 5);
    int lane = threadIdx.x & 31;
    if (warp >= NROWS) return;
    int rr = warp;                     // rr = s*BATCH + b
    int tok = sent32[g_flag ? rr : 2 * rr];
    const float* xr = emb + (long)tok * EDIM;
    float x0 = xr[lane];
    float x1 = xr[32 + lane];
    const float* wrow = Win + lane * 72;   // Win[(g,q)=lane][f]
    float acc = b_in[lane] + phi[lane];
#pragma unroll
    for (int f = 0; f < 32; f++) acc = fmaf(wrow[f],      __shfl_sync(FULLM, x0, f), acc);
#pragma unroll
    for (int f = 0; f < 32; f++) acc = fmaf(wrow[32 + f], __shfl_sync(FULLM, x1, f), acc);
    g_Zx[rr * 32 + lane] = acc;
}

// ============================================================================
// Kernel C: sequential recurrence. One warp per batch element (128 warps).
// lane = g*8 + q  (for z / qprod)  and  g*8 + h (for pre)
// ============================================================================
__global__ void k_recur(const float* __restrict__ Win,
                        const float* __restrict__ Wout,
                        const float* __restrict__ b_out) {
    int b    = blockIdx.x;
    int lane = threadIdx.x & 31;
    int g    = lane >> 3;
    int q    = lane & 7;

    float Wh[8];
#pragma unroll
    for (int j = 0; j < 8; j++) Wh[j] = Win[lane * 72 + 64 + j];
    float Wo[8];
#pragma unroll
    for (int j = 0; j < 8; j++) Wo[j] = Wout[g * 64 + q * 8 + j];  // Wout[g][h=q][j]
    float bo = b_out[lane];   // b_out[g][h=q] at flat index lane

    float hbc[8];
#pragma unroll
    for (int j = 0; j < 8; j++) hbc[j] = 0.f;
    float cstate = 0.f;       // lane holds c for column (lane&7); 4 consistent replicas

    for (int s = 0; s < S_LEN; s++) {
        float z = g_Zx[(s * BATCH + b) * 32 + lane];
#pragma unroll
        for (int j = 0; j < 8; j++) z = fmaf(Wh[j], hbc[j], z);
        float p = cosf(z);
        // inclusive cumprod within 8-lane groups
#pragma unroll
        for (int d = 1; d < 8; d <<= 1) {
            float t = __shfl_up_sync(FULLM, p, d, 8);
            if ((lane & 7) >= d) p *= t;
        }
        // pre[g][h]: lane (g,h=q) gathers q-values of its gate group
        float pre = bo;
#pragma unroll
        for (int j = 0; j < 8; j++)
            pre = fmaf(Wo[j], __shfl_sync(FULLM, p, (lane & 24) + j), pre);
        float act = (g == 2) ? tanhf(pre) : 1.f / (1.f + expf(-pre));
        int h = lane & 7;
        float fv = __shfl_sync(FULLM, act, h);
        float iv = __shfl_sync(FULLM, act, 8 + h);
        float gv = __shfl_sync(FULLM, act, 16 + h);
        float ov = __shfl_sync(FULLM, act, 24 + h);
        cstate = fmaf(fv, cstate, iv * gv);
        float hval = ov * tanhf(cstate);
#pragma unroll
        for (int j = 0; j < 8; j++) hbc[j] = __shfl_sync(FULLM, hval, j);
        if (lane < 8) g_hs[(s * BATCH + b) * HDIM + lane] = hval;
    }
}

// ============================================================================
// Kernel D: quantum head. One warp per output row (16384 warps).
// 256 amps: lane holds amps m = lane*8 + k. wire w <-> bit (7-w).
// bits 7..3 = lane bits (wires 0..4), bits 2..0 = intra-lane (wires 5..7).
// ============================================================================
__device__ __forceinline__ void rot_lane(float* ar, float* ai, int b, float c, float s,
                                         int isRX, int lane) {
    int delta = 1 << (b - 3);
    int side  = (lane >> (b - 3)) & 1;
    float sgn = side ? s : -s;
#pragma unroll
    for (int k = 0; k < 8; k++) {
        float pr = __shfl_xor_sync(FULLM, ar[k], delta);
        float pi = __shfl_xor_sync(FULLM, ai[k], delta);
        if (isRX) {
            float nr = fmaf(s, pi, c * ar[k]);
            float ni = fmaf(-s, pr, c * ai[k]);
            ar[k] = nr; ai[k] = ni;
        } else {
            ar[k] = fmaf(sgn, pr, c * ar[k]);
            ai[k] = fmaf(sgn, pi, c * ai[k]);
        }
    }
}

template<int M>
__device__ __forceinline__ void rot_intra_t(float* ar, float* ai, float c, float s, int isRX) {
#pragma unroll
    for (int k = 0; k < 8; k++) {
        if (!(k & M)) {
            const int k1 = k | M;
            float a0r = ar[k], a0i = ai[k], a1r = ar[k1], a1i = ai[k1];
            if (isRX) {
                ar[k]  = fmaf(s, a1i, c * a0r);  ai[k]  = fmaf(-s, a1r, c * a0i);
                ar[k1] = fmaf(s, a0i, c * a1r);  ai[k1] = fmaf(-s, a0r, c * a1i);
            } else {
                ar[k]  = fmaf(-s, a1r, c * a0r); ai[k]  = fmaf(-s, a1i, c * a0i);
                ar[k1] = fmaf( s, a0r, c * a1r); ai[k1] = fmaf( s, a0i, c * a1i);
            }
        }
    }
}

__device__ __forceinline__ void rz_any(float* ar, float* ai, int b, float c, float s, int lane) {
#pragma unroll
    for (int k = 0; k < 8; k++) {
        int m = (lane << 3) | k;
        float sg = ((m >> b) & 1) ? -s : s;
        float nr = fmaf(sg, ai[k], c * ar[k]);
        float ni = fmaf(-sg, ar[k], c * ai[k]);
        ar[k] = nr; ai[k] = ni;
    }
}

template<int MT_>
__device__ __forceinline__ void cnot_cl_ti(float* ar, float* ai, int ctrl) {
    if (ctrl) {
#pragma unroll
        for (int k = 0; k < 8; k++) if (!(k & MT_)) {
            const int k1 = k | MT_;
            float tr = ar[k]; ar[k] = ar[k1]; ar[k1] = tr;
            float ti = ai[k]; ai[k] = ai[k1]; ai[k1] = ti;
        }
    }
}
template<int MC>
__device__ __forceinline__ void cnot_ci_tl(float* ar, float* ai, int delta) {
#pragma unroll
    for (int k = 0; k < 8; k++) if (k & MC) {
        ar[k] = __shfl_xor_sync(FULLM, ar[k], delta);
        ai[k] = __shfl_xor_sync(FULLM, ai[k], delta);
    }
}
template<int MC, int MT_>
__device__ __forceinline__ void cnot_ii(float* ar, float* ai) {
#pragma unroll
    for (int k = 0; k < 8; k++) if ((k & MC) && !(k & MT_)) {
        const int k1 = k | MT_;
        float tr = ar[k]; ar[k] = ar[k1]; ar[k1] = tr;
        float ti = ai[k]; ai[k] = ai[k1]; ai[k1] = ti;
    }
}

__device__ __forceinline__ void cnot_apply(float* ar, float* ai, int bc, int bt, int lane) {
    if (bc >= 3 && bt >= 3) {
        int delta = 1 << (bt - 3);
        int ctrl = (lane >> (bc - 3)) & 1;
#pragma unroll
        for (int k = 0; k < 8; k++) {
            float pr = __shfl_xor_sync(FULLM, ar[k], delta);
            float pi = __shfl_xor_sync(FULLM, ai[k], delta);
            if (ctrl) { ar[k] = pr; ai[k] = pi; }
        }
    } else if (bc >= 3) {
        int ctrl = (lane >> (bc - 3)) & 1;
        if      (bt == 0) cnot_cl_ti<1>(ar, ai, ctrl);
        else if (bt == 1) cnot_cl_ti<2>(ar, ai, ctrl);
        else              cnot_cl_ti<4>(ar, ai, ctrl);
    } else if (bt >= 3) {
        int delta = 1 << (bt - 3);
        if      (bc == 0) cnot_ci_tl<1>(ar, ai, delta);
        else if (bc == 1) cnot_ci_tl<2>(ar, ai, delta);
        else              cnot_ci_tl<4>(ar, ai, delta);
    } else {
        int code = bc * 3 + bt;
        switch (code) {
            case 1: cnot_ii<1, 2>(ar, ai); break;   // bc=0 bt=1
            case 2: cnot_ii<1, 4>(ar, ai); break;   // bc=0 bt=2
            case 3: cnot_ii<2, 1>(ar, ai); break;   // bc=1 bt=0
            case 5: cnot_ii<2, 4>(ar, ai); break;   // bc=1 bt=2
            case 6: cnot_ii<4, 1>(ar, ai); break;   // bc=2 bt=0
            default: cnot_ii<4, 2>(ar, ai); break;  // bc=2 bt=1
        }
    }
}

__global__ void __launch_bounds__(256) k_head(const float* __restrict__ phiq,
                                              const float* __restrict__ Whead,
                                              const float* __restrict__ b_head,
                                              float* __restrict__ out,
                                              OpsParam P) {
    int warp = blockIdx.x * (blockDim.x >> 5) + (threadIdx.x >> 5);
    int lane = threadIdx.x & 31;
    if (warp >= NROWS) return;
    int r  = warp;
    int sp = r >> 7;        // s'
    int bp = r & 127;       // b'
    // out[s'][b'] <- hidden at (s = b', batch = s')   (batch-major reshape algebra)
    int hoff = ((bp << 7) + sp) * HDIM;

    // ---- encode: product state from RY angles ----
    float ce = 1.f, se = 0.f;
    if (lane < 8) {
        float th = 0.5f * g_hs[hoff + lane];
        sincosf(th, &se, &ce);
    }
    float Fl = 1.f;
#pragma unroll
    for (int w = 0; w < 5; w++) {
        float cw = __shfl_sync(FULLM, ce, w);
        float sw = __shfl_sync(FULLM, se, w);
        Fl *= ((lane >> (4 - w)) & 1) ? sw : cw;
    }
    float c5 = __shfl_sync(FULLM, ce, 5), s5v = __shfl_sync(FULLM, se, 5);
    float c6 = __shfl_sync(FULLM, ce, 6), s6v = __shfl_sync(FULLM, se, 6);
    float c7 = __shfl_sync(FULLM, ce, 7), s7v = __shfl_sync(FULLM, se, 7);
    float ar[8], ai[8];
#pragma unroll
    for (int k = 0; k < 8; k++) {
        float f = ((k & 4) ? s5v : c5) * ((k & 2) ? s6v : c6) * ((k & 1) ? s7v : c7);
        ar[k] = Fl * f; ai[k] = 0.f;
    }

    // ---- fixed random layer ----
    for (int i = 0; i < P.n; i++) {
        int ty = P.type[i];
        if (ty == 3) {
            cnot_apply(ar, ai, 7 - P.pa[i], 7 - P.pb[i], lane);
        } else {
            int bb = 7 - P.pa[i];
            float c = P.c[i], s = P.s[i];
            if (ty == 2)        rz_any(ar, ai, bb, c, s, lane);
            else if (bb >= 3)   rot_lane(ar, ai, bb, c, s, ty == 0, lane);
            else if (bb == 2)   rot_intra_t<4>(ar, ai, c, s, ty == 0);
            else if (bb == 1)   rot_intra_t<2>(ar, ai, c, s, ty == 0);
            else                rot_intra_t<1>(ar, ai, c, s, ty == 0);
        }
    }

    // ---- trainable RX(phiq) on every wire ----
    float cq = 1.f, sq = 0.f;
    if (lane < 8) {
        float th = 0.5f * phiq[lane];
        sincosf(th, &sq, &cq);
    }
#pragma unroll
    for (int w = 0; w < 8; w++) {
        float c = __shfl_sync(FULLM, cq, w);
        float s = __shfl_sync(FULLM, sq, w);
        const int bb = 7 - w;
        if (bb >= 3)       rot_lane(ar, ai, bb, c, s, 1, lane);
        else if (bb == 2)  rot_intra_t<4>(ar, ai, c, s, 1);
        else if (bb == 1)  rot_intra_t<2>(ar, ai, c, s, 1);
        else               rot_intra_t<1>(ar, ai, c, s, 1);
    }

    // ---- measure <Z_w> ----
    float p[8];
#pragma unroll
    for (int k = 0; k < 8; k++) p[k] = fmaf(ar[k], ar[k], ai[k] * ai[k]);
    float tot = 0.f, s5 = 0.f, s6 = 0.f, s7 = 0.f;
#pragma unroll
    for (int k = 0; k < 8; k++) {
        tot += p[k];
        s5 += (k & 4) ? -p[k] : p[k];
        s6 += (k & 2) ? -p[k] : p[k];
        s7 += (k & 1) ? -p[k] : p[k];
    }
    float z[8];
#pragma unroll
    for (int w = 0; w < 8; w++) {
        float v;
        if (w < 5)      v = ((lane >> (4 - w)) & 1) ? -tot : tot;
        else if (w == 5) v = s5;
        else if (w == 6) v = s6;
        else             v = s7;
#pragma unroll
        for (int d = 16; d >= 1; d >>= 1) v += __shfl_xor_sync(FULLM, v, d);
        z[w] = v;
    }

    // ---- logits + log_softmax over T=12 ----
    float lg = 0.f;
    if (lane < TDIM) {
        lg = b_head[lane];
#pragma unroll
        for (int k = 0; k < 8; k++) lg = fmaf(z[k], Whead[lane * 8 + k], lg);
    }
    float mv = (lane < TDIM) ? lg : -3.0e38f;
#pragma unroll
    for (int d = 16; d >= 1; d >>= 1) mv = fmaxf(mv, __shfl_xor_sync(FULLM, mv, d));
    float ev = (lane < TDIM) ? expf(lg - mv) : 0.f;
#pragma unroll
    for (int d = 16; d >= 1; d >>= 1) ev += __shfl_xor_sync(FULLM, ev, d);
    if (lane < TDIM) out[r * TDIM + lane] = lg - mv - logf(ev);
}

// ============================================================================
// Launch
// ============================================================================
extern "C" void kernel_launch(void* const* d_in, const int* in_sizes, int n_in,
                              void* d_out, int out_size) {
    (void)in_sizes; (void)n_in; (void)out_size;
    const float* emb    = (const float*)d_in[0];
    const float* Win    = (const float*)d_in[1];
    const float* b_in   = (const float*)d_in[2];
    const float* phi    = (const float*)d_in[3];
    const float* Wout   = (const float*)d_in[4];
    const float* b_out  = (const float*)d_in[5];
    const float* phiq   = (const float*)d_in[6];
    const float* Whead  = (const float*)d_in[7];
    const float* b_head = (const float*)d_in[8];
    const int*   sent32 = (const int*)d_in[9];
    float* out = (float*)d_out;

    OpsParam P;
    build_ops(P);   // deterministic; recomputed every call (cheap), baked into graph

    k_detect<<<1, 256>>>(sent32);
    k_project<<<NROWS / 8, 256>>>(emb, Win, b_in, phi, sent32);
    k_recur<<<BATCH, 32>>>(Win, Wout, b_out);
    k_head<<<NROWS / 8, 256>>>(phiq, Whead, b_head, out, P);
}

// round 4
// speedup vs baseline: 1.2424x; 1.2424x over previous
#include <cuda_runtime.h>
#include <cstdint>
#include <math.h>

// Problem constants
#define S_LEN  128
#define BATCH  128
#define EDIM   64
#define HDIM   8
#define TDIM   12
#define NROWS  (S_LEN*BATCH)   // 16384
#define FULLM  0xffffffffu

// -------------------- device scratch (no allocations allowed) ---------------
__device__ float g_Zx[NROWS * 32];    // per-(s,b) input projection (+b_in+phi), 2 MB
__device__ float g_hs[NROWS * HDIM];  // hidden states hs[s][b][h], 512 KB
__device__ int   g_flag;              // 1 => sentence buffer is int32, 0 => int64

// ============================================================================
// Host-side: numpy-legacy MT19937 reproduction for _build_random_layer(seed=1234)
// ============================================================================
namespace mtrng {
struct MT { uint32_t key[624]; int pos; };
static void mt_seed(MT& st, uint32_t s) {
    for (int i = 0; i < 624; i++) { st.key[i] = s; s = 1812433253u * (s ^ (s >> 30)) + (uint32_t)i + 1u; }
    st.pos = 624;
}
static void mt_gen(MT& st) {
    int i; uint32_t y;
    for (i = 0; i < 624 - 397; i++) {
        y = (st.key[i] & 0x80000000u) | (st.key[i + 1] & 0x7fffffffu);
        st.key[i] = st.key[i + 397] ^ (y >> 1) ^ ((y & 1u) ? 0x9908b0dfu : 0u);
    }
    for (; i < 623; i++) {
        y = (st.key[i] & 0x80000000u) | (st.key[i + 1] & 0x7fffffffu);
        st.key[i] = st.key[i - 227] ^ (y >> 1) ^ ((y & 1u) ? 0x9908b0dfu : 0u);
    }
    y = (st.key[623] & 0x80000000u) | (st.key[0] & 0x7fffffffu);
    st.key[623] = st.key[396] ^ (y >> 1) ^ ((y & 1u) ? 0x9908b0dfu : 0u);
    st.pos = 0;
}
static uint32_t mt_next(MT& st) {
    if (st.pos == 624) mt_gen(st);
    uint32_t y = st.key[st.pos++];
    y ^= y >> 11; y ^= (y << 7) & 0x9d2c5680u; y ^= (y << 15) & 0xefc60000u; y ^= y >> 18;
    return y;
}
static int mt_randint(MT& st, uint32_t n) {
    uint32_t rng = n - 1u;
    uint32_t mask = rng;
    mask |= mask >> 1; mask |= mask >> 2; mask |= mask >> 4; mask |= mask >> 8; mask |= mask >> 16;
    uint32_t v;
    do { v = mt_next(st) & mask; } while (v > rng);
    return (int)v;
}
static double mt_double(MT& st) {
    uint32_t a = mt_next(st) >> 5, b = mt_next(st) >> 6;
    return ((double)a * 67108864.0 + (double)b) / 9007199254740992.0;
}
} // namespace mtrng

struct OpsParam {
    int   type[32];  // 0 rx, 1 ry, 2 rz, 3 cnot
    int   pa[32];    // wire / control
    int   pb[32];    // target (cnot)
    float c[32], s[32];  // cos(theta/2), sin(theta/2)
    int   n;
};

static void build_ops(OpsParam& P) {
    mtrng::MT st; mtrng::mt_seed(st, 1234u);
    int n = 0;
    for (int i = 0; i < 30; i++) {
        int kind = mtrng::mt_randint(st, 4);
        if (kind == 3) {
            int c = mtrng::mt_randint(st, 8);
            int t = mtrng::mt_randint(st, 7);
            if (t >= c) t += 1;
            P.type[n] = 3; P.pa[n] = c; P.pb[n] = t; P.c[n] = 0.f; P.s[n] = 0.f; n++;
        } else {
            int g = kind % 3;                 // 0 rx, 1 ry, 2 rz
            int w = mtrng::mt_randint(st, 8);
            double ang = mtrng::mt_double(st) * (2.0 * M_PI);
            float th = (float)ang;            // reference casts to float32
            double half = (double)(th * 0.5f);
            P.type[n] = g; P.pa[n] = w; P.pb[n] = -1;
            P.c[n] = (float)cos(half); P.s[n] = (float)sin(half); n++;
        }
    }
    P.n = n;
}

// ============================================================================
// Kernel A: detect sentence dtype (int64 vs int32) without host readback
// ============================================================================
__global__ void k_detect(const int4* __restrict__ sent4) {
    __shared__ int any;
    if (threadIdx.x == 0) any = 0;
    __syncthreads();
    int loc = 0;
    for (int i = threadIdx.x; i < 4096; i += blockDim.x) {
        int4 v = sent4[i];
        loc |= v.y | v.w;   // high words if int64 (all zero), real tokens if int32
    }
    if (loc) atomicOr(&any, 1);
    __syncthreads();
    if (threadIdx.x == 0) g_flag = any ? 1 : 0;   // 1 => int32 data
}

// ============================================================================
// Kernel B: embed-gather + input projection  Zx[s][b][32] = Win_x·x + b_in + phi
// ============================================================================
__global__ void k_project(const float* __restrict__ emb,
                          const float* __restrict__ Win,
                          const float* __restrict__ b_in,
                          const float* __restrict__ phi,
                          const int*   __restrict__ sent32) {
    int warp = blockIdx.x * (blockDim.x >> 5) + (threadIdx.x >> 5);
    int lane = threadIdx.x & 31;
    if (warp >= NROWS) return;
    int rr = warp;                     // rr = s*BATCH + b
    int tok = sent32[g_flag ? rr : 2 * rr];
    const float* xr = emb + (long)tok * EDIM;
    float x0 = xr[lane];
    float x1 = xr[32 + lane];
    const float* wrow = Win + lane * 72;   // Win[(g,q)=lane][f]
    float acc = b_in[lane] + phi[lane];
#pragma unroll
    for (int f = 0; f < 32; f++) acc = fmaf(wrow[f],      __shfl_sync(FULLM, x0, f), acc);
#pragma unroll
    for (int f = 0; f < 32; f++) acc = fmaf(wrow[32 + f], __shfl_sync(FULLM, x1, f), acc);
    g_Zx[rr * 32 + lane] = acc;
}

// ============================================================================
// Kernel C: sequential recurrence. One warp per batch element (128 warps).
// lane = g*8 + q. Latency-optimized: fast transcendentals, fused cumprod-dot,
// uniform activation, one-step-ahead Zx prefetch.
// ============================================================================
__global__ void k_recur(const float* __restrict__ Win,
                        const float* __restrict__ Wout,
                        const float* __restrict__ b_out) {
    int b    = blockIdx.x;
    int lane = threadIdx.x & 31;
    int g    = lane >> 3;
    int q    = lane & 7;

    float Wh[8];
#pragma unroll
    for (int j = 0; j < 8; j++) Wh[j] = Win[lane * 72 + 64 + j];
    float Wo[8];
#pragma unroll
    for (int j = 0; j < 8; j++) Wo[j] = Wout[g * 64 + q * 8 + j];  // Wout[g][h=q][j]
    float bo = b_out[lane];

    // uniform activation: act = am * sigmoid(am * pre) + aa
    float am = (g == 2) ? 2.f : 1.f;
    float aa = (g == 2) ? -1.f : 0.f;

    float h[8];
#pragma unroll
    for (int j = 0; j < 8; j++) h[j] = 0.f;
    float cst = 0.f;

    const float* Zp = g_Zx + b * 32 + lane;     // stride per step: BATCH*32 floats
    float zin = Zp[0];

    for (int s = 0; s < S_LEN; s++) {
        // prefetch next step's projection (L2-resident; hidden behind this step)
        float znext = (s + 1 < S_LEN) ? Zp[(s + 1) * (BATCH * 32)] : 0.f;

        // z = zin + Wh·h   (two accumulator chains)
        float za = zin, zb = 0.f;
#pragma unroll
        for (int j = 0; j < 8; j += 2) {
            za = fmaf(Wh[j],     h[j],     za);
            zb = fmaf(Wh[j + 1], h[j + 1], zb);
        }
        float p = __cosf(za + zb);

        // gather this gate-group's 8 cos values (independent shfls)
        float pg[8];
#pragma unroll
        for (int j = 0; j < 8; j++)
            pg[j] = __shfl_sync(FULLM, p, (lane & 24) + j);

        // fused cumprod + Wout dot
        float cum = pg[0];
        float pre = fmaf(Wo[0], cum, bo);
#pragma unroll
        for (int j = 1; j < 8; j++) {
            cum *= pg[j];
            pre = fmaf(Wo[j], cum, pre);
        }

        // act: sigmoid for gates f,i,o ; tanh (=2σ(2x)-1) for g
        float xx = am * pre;
        float sg = __fdividef(1.f, 1.f + __expf(-xx));
        float act = fmaf(am, sg, aa);

        float fv = __shfl_sync(FULLM, act, q);
        float iv = __shfl_sync(FULLM, act, 8 + q);
        float gv = __shfl_sync(FULLM, act, 16 + q);
        float ov = __shfl_sync(FULLM, act, 24 + q);
        cst = fmaf(fv, cst, iv * gv);
        // tanh(c) = 2σ(2c)-1
        float tc = fmaf(2.f, __fdividef(1.f, 1.f + __expf(-2.f * cst)), -1.f);
        float hval = ov * tc;

        if (lane < 8) g_hs[(s * BATCH + b) * HDIM + lane] = hval;
#pragma unroll
        for (int j = 0; j < 8; j++) h[j] = __shfl_sync(FULLM, hval, j);
        zin = znext;
    }
}

// ============================================================================
// Kernel D: quantum head. One warp per output row (16384 warps).
// 256 amps: lane holds amps m = lane*8 + k. wire w <-> bit (7-w).
// bits 7..3 = lane bits (wires 0..4), bits 2..0 = intra-lane (wires 5..7).
// ============================================================================
__device__ __forceinline__ void rot_lane(float* ar, float* ai, int b, float c, float s,
                                         int isRX, int lane) {
    int delta = 1 << (b - 3);
    int side  = (lane >> (b - 3)) & 1;
    float sgn = side ? s : -s;
#pragma unroll
    for (int k = 0; k < 8; k++) {
        float pr = __shfl_xor_sync(FULLM, ar[k], delta);
        float pi = __shfl_xor_sync(FULLM, ai[k], delta);
        if (isRX) {
            float nr = fmaf(s, pi, c * ar[k]);
            float ni = fmaf(-s, pr, c * ai[k]);
            ar[k] = nr; ai[k] = ni;
        } else {
            ar[k] = fmaf(sgn, pr, c * ar[k]);
            ai[k] = fmaf(sgn, pi, c * ai[k]);
        }
    }
}

template<int M>
__device__ __forceinline__ void rot_intra_t(float* ar, float* ai, float c, float s, int isRX) {
#pragma unroll
    for (int k = 0; k < 8; k++) {
        if (!(k & M)) {
            const int k1 = k | M;
            float a0r = ar[k], a0i = ai[k], a1r = ar[k1], a1i = ai[k1];
            if (isRX) {
                ar[k]  = fmaf(s, a1i, c * a0r);  ai[k]  = fmaf(-s, a1r, c * a0i);
                ar[k1] = fmaf(s, a0i, c * a1r);  ai[k1] = fmaf(-s, a0r, c * a1i);
            } else {
                ar[k]  = fmaf(-s, a1r, c * a0r); ai[k]  = fmaf(-s, a1i, c * a0i);
                ar[k1] = fmaf( s, a0r, c * a1r); ai[k1] = fmaf( s, a0i, c * a1i);
            }
        }
    }
}

__device__ __forceinline__ void rz_any(float* ar, float* ai, int b, float c, float s, int lane) {
#pragma unroll
    for (int k = 0; k < 8; k++) {
        int m = (lane << 3) | k;
        float sg = ((m >> b) & 1) ? -s : s;
        float nr = fmaf(sg, ai[k], c * ar[k]);
        float ni = fmaf(-sg, ar[k], c * ai[k]);
        ar[k] = nr; ai[k] = ni;
    }
}

template<int MT_>
__device__ __forceinline__ void cnot_cl_ti(float* ar, float* ai, int ctrl) {
    if (ctrl) {
#pragma unroll
        for (int k = 0; k < 8; k++) if (!(k & MT_)) {
            const int k1 = k | MT_;
            float tr = ar[k]; ar[k] = ar[k1]; ar[k1] = tr;
            float ti = ai[k]; ai[k] = ai[k1]; ai[k1] = ti;
        }
    }
}
template<int MC>
__device__ __forceinline__ void cnot_ci_tl(float* ar, float* ai, int delta) {
#pragma unroll
    for (int k = 0; k < 8; k++) if (k & MC) {
        ar[k] = __shfl_xor_sync(FULLM, ar[k], delta);
        ai[k] = __shfl_xor_sync(FULLM, ai[k], delta);
    }
}
template<int MC, int MT_>
__device__ __forceinline__ void cnot_ii(float* ar, float* ai) {
#pragma unroll
    for (int k = 0; k < 8; k++) if ((k & MC) && !(k & MT_)) {
        const int k1 = k | MT_;
        float tr = ar[k]; ar[k] = ar[k1]; ar[k1] = tr;
        float ti = ai[k]; ai[k] = ai[k1]; ai[k1] = ti;
    }
}

__device__ __forceinline__ void cnot_apply(float* ar, float* ai, int bc, int bt, int lane) {
    if (bc >= 3 && bt >= 3) {
        int delta = 1 << (bt - 3);
        int ctrl = (lane >> (bc - 3)) & 1;
#pragma unroll
        for (int k = 0; k < 8; k++) {
            float pr = __shfl_xor_sync(FULLM, ar[k], delta);
            float pi = __shfl_xor_sync(FULLM, ai[k], delta);
            if (ctrl) { ar[k] = pr; ai[k] = pi; }
        }
    } else if (bc >= 3) {
        int ctrl = (lane >> (bc - 3)) & 1;
        if      (bt == 0) cnot_cl_ti<1>(ar, ai, ctrl);
        else if (bt == 1) cnot_cl_ti<2>(ar, ai, ctrl);
        else              cnot_cl_ti<4>(ar, ai, ctrl);
    } else if (bt >= 3) {
        int delta = 1 << (bt - 3);
        if      (bc == 0) cnot_ci_tl<1>(ar, ai, delta);
        else if (bc == 1) cnot_ci_tl<2>(ar, ai, delta);
        else              cnot_ci_tl<4>(ar, ai, delta);
    } else {
        int code = bc * 3 + bt;
        switch (code) {
            case 1: cnot_ii<1, 2>(ar, ai); break;   // bc=0 bt=1
            case 2: cnot_ii<1, 4>(ar, ai); break;   // bc=0 bt=2
            case 3: cnot_ii<2, 1>(ar, ai); break;   // bc=1 bt=0
            case 5: cnot_ii<2, 4>(ar, ai); break;   // bc=1 bt=2
            case 6: cnot_ii<4, 1>(ar, ai); break;   // bc=2 bt=0
            default: cnot_ii<4, 2>(ar, ai); break;  // bc=2 bt=1
        }
    }
}

__global__ void __launch_bounds__(256) k_head(const float* __restrict__ phiq,
                                              const float* __restrict__ Whead,
                                              const float* __restrict__ b_head,
                                              float* __restrict__ out,
                                              OpsParam P) {
    int warp = blockIdx.x * (blockDim.x >> 5) + (threadIdx.x >> 5);
    int lane = threadIdx.x & 31;
    if (warp >= NROWS) return;
    int r  = warp;
    int sp = r >> 7;        // s'
    int bp = r & 127;       // b'
    // out[s'][b'] <- hidden at (s = b', batch = s')   (batch-major reshape algebra)
    int hoff = ((bp << 7) + sp) * HDIM;

    // ---- encode: product state from RY angles ----
    float ce = 1.f, se = 0.f;
    if (lane < 8) {
        float th = 0.5f * g_hs[hoff + lane];
        __sincosf(th, &se, &ce);
    }
    float Fl = 1.f;
#pragma unroll
    for (int w = 0; w < 5; w++) {
        float cw = __shfl_sync(FULLM, ce, w);
        float sw = __shfl_sync(FULLM, se, w);
        Fl *= ((lane >> (4 - w)) & 1) ? sw : cw;
    }
    float c5 = __shfl_sync(FULLM, ce, 5), s5v = __shfl_sync(FULLM, se, 5);
    float c6 = __shfl_sync(FULLM, ce, 6), s6v = __shfl_sync(FULLM, se, 6);
    float c7 = __shfl_sync(FULLM, ce, 7), s7v = __shfl_sync(FULLM, se, 7);
    float ar[8], ai[8];
#pragma unroll
    for (int k = 0; k < 8; k++) {
        float f = ((k & 4) ? s5v : c5) * ((k & 2) ? s6v : c6) * ((k & 1) ? s7v : c7);
        ar[k] = Fl * f; ai[k] = 0.f;
    }

    // ---- fixed random layer ----
    for (int i = 0; i < P.n; i++) {
        int ty = P.type[i];
        if (ty == 3) {
            cnot_apply(ar, ai, 7 - P.pa[i], 7 - P.pb[i], lane);
        } else {
            int bb = 7 - P.pa[i];
            float c = P.c[i], s = P.s[i];
            if (ty == 2)        rz_any(ar, ai, bb, c, s, lane);
            else if (bb >= 3)   rot_lane(ar, ai, bb, c, s, ty == 0, lane);
            else if (bb == 2)   rot_intra_t<4>(ar, ai, c, s, ty == 0);
            else if (bb == 1)   rot_intra_t<2>(ar, ai, c, s, ty == 0);
            else                rot_intra_t<1>(ar, ai, c, s, ty == 0);
        }
    }

    // ---- trainable RX(phiq) on every wire ----
    float cq = 1.f, sq = 0.f;
    if (lane < 8) {
        float th = 0.5f * phiq[lane];
        __sincosf(th, &sq, &cq);
    }
#pragma unroll
    for (int w = 0; w < 8; w++) {
        float c = __shfl_sync(FULLM, cq, w);
        float s = __shfl_sync(FULLM, sq, w);
        const int bb = 7 - w;
        if (bb >= 3)       rot_lane(ar, ai, bb, c, s, 1, lane);
        else if (bb == 2)  rot_intra_t<4>(ar, ai, c, s, 1);
        else if (bb == 1)  rot_intra_t<2>(ar, ai, c, s, 1);
        else               rot_intra_t<1>(ar, ai, c, s, 1);
    }

    // ---- measure <Z_w> ----
    float p[8];
#pragma unroll
    for (int k = 0; k < 8; k++) p[k] = fmaf(ar[k], ar[k], ai[k] * ai[k]);
    float tot = 0.f, s5 = 0.f, s6 = 0.f, s7 = 0.f;
#pragma unroll
    for (int k = 0; k < 8; k++) {
        tot += p[k];
        s5 += (k & 4) ? -p[k] : p[k];
        s6 += (k & 2) ? -p[k] : p[k];
        s7 += (k & 1) ? -p[k] : p[k];
    }
    float z[8];
#pragma unroll
    for (int w = 0; w < 8; w++) {
        float v;
        if (w < 5)      v = ((lane >> (4 - w)) & 1) ? -tot : tot;
        else if (w == 5) v = s5;
        else if (w == 6) v = s6;
        else             v = s7;
#pragma unroll
        for (int d = 16; d >= 1; d >>= 1) v += __shfl_xor_sync(FULLM, v, d);
        z[w] = v;
    }

    // ---- logits + log_softmax over T=12 ----
    float lg = 0.f;
    if (lane < TDIM) {
        lg = b_head[lane];
#pragma unroll
        for (int k = 0; k < 8; k++) lg = fmaf(z[k], Whead[lane * 8 + k], lg);
    }
    float mv = (lane < TDIM) ? lg : -3.0e38f;
#pragma unroll
    for (int d = 16; d >= 1; d >>= 1) mv = fmaxf(mv, __shfl_xor_sync(FULLM, mv, d));
    float ev = (lane < TDIM) ? __expf(lg - mv) : 0.f;
#pragma unroll
    for (int d = 16; d >= 1; d >>= 1) ev += __shfl_xor_sync(FULLM, ev, d);
    if (lane < TDIM) out[r * TDIM + lane] = lg - mv - __logf(ev);
}

// ============================================================================
// Launch
// ============================================================================
extern "C" void kernel_launch(void* const* d_in, const int* in_sizes, int n_in,
                              void* d_out, int out_size) {
    (void)in_sizes; (void)n_in; (void)out_size;
    const float* emb    = (const float*)d_in[0];
    const float* Win    = (const float*)d_in[1];
    const float* b_in   = (const float*)d_in[2];
    const float* phi    = (const float*)d_in[3];
    const float* Wout   = (const float*)d_in[4];
    const float* b_out  = (const float*)d_in[5];
    const float* phiq   = (const float*)d_in[6];
    const float* Whead  = (const float*)d_in[7];
    const float* b_head = (const float*)d_in[8];
    const int*   sent32 = (const int*)d_in[9];
    float* out = (float*)d_out;

    OpsParam P;
    build_ops(P);   // deterministic; recomputed every call (cheap), baked into graph

    k_detect<<<1, 256>>>((const int4*)sent32);
    k_project<<<NROWS / 8, 256>>>(emb, Win, b_in, phi, sent32);
    k_recur<<<BATCH, 32>>>(Win, Wout, b_out);
    k_head<<<NROWS / 8, 256>>>(phiq, Whead, b_head, out, P);
}

// round 5
// speedup vs baseline: 1.4598x; 1.1750x over previous
#include <cuda_runtime.h>
#include <cstdint>
#include <math.h>

// Problem constants
#define S_LEN  128
#define BATCH  128
#define EDIM   64
#define HDIM   8
#define TDIM   12
#define NROWS  (S_LEN*BATCH)   // 16384
#define FULLM  0xffffffffu
#define NOPS   30

// -------------------- device scratch (no allocations allowed) ---------------
__device__ float g_Zx[NROWS * 32];    // per-(s,b) input projection (+b_in+phi), 2 MB
__device__ float g_hs[NROWS * HDIM];  // hidden states hs[s][b][h], 512 KB
__device__ int   g_flag;              // 1 => sentence buffer is int32, 0 => int64
__device__ float g_phiq_c[8], g_phiq_s[8];

// ============================================================================
// numpy-legacy MT19937 — constexpr so the circuit STRUCTURE is compile-time.
// ============================================================================
namespace mtrng {
struct MT { uint32_t key[624]; int pos; };
constexpr void mt_seed(MT& st, uint32_t s) {
    for (int i = 0; i < 624; i++) { st.key[i] = s; s = 1812433253u * (s ^ (s >> 30)) + (uint32_t)i + 1u; }
    st.pos = 624;
}
constexpr void mt_gen(MT& st) {
    int i = 0; uint32_t y = 0;
    for (i = 0; i < 624 - 397; i++) {
        y = (st.key[i] & 0x80000000u) | (st.key[i + 1] & 0x7fffffffu);
        st.key[i] = st.key[i + 397] ^ (y >> 1) ^ ((y & 1u) ? 0x9908b0dfu : 0u);
    }
    for (; i < 623; i++) {
        y = (st.key[i] & 0x80000000u) | (st.key[i + 1] & 0x7fffffffu);
        st.key[i] = st.key[i - 227] ^ (y >> 1) ^ ((y & 1u) ? 0x9908b0dfu : 0u);
    }
    y = (st.key[623] & 0x80000000u) | (st.key[0] & 0x7fffffffu);
    st.key[623] = st.key[396] ^ (y >> 1) ^ ((y & 1u) ? 0x9908b0dfu : 0u);
    st.pos = 0;
}
constexpr uint32_t mt_next(MT& st) {
    if (st.pos == 624) mt_gen(st);
    uint32_t y = st.key[st.pos++];
    y ^= y >> 11; y ^= (y << 7) & 0x9d2c5680u; y ^= (y << 15) & 0xefc60000u; y ^= y >> 18;
    return y;
}
constexpr int mt_randint(MT& st, uint32_t n) {
    uint32_t rng = n - 1u;
    uint32_t mask = rng;
    mask |= mask >> 1; mask |= mask >> 2; mask |= mask >> 4; mask |= mask >> 8; mask |= mask >> 16;
    uint32_t v = 0;
    do { v = mt_next(st) & mask; } while (v > rng);
    return (int)v;
}
constexpr double mt_double(MT& st) {
    uint32_t a = mt_next(st) >> 5, b = mt_next(st) >> 6;
    return ((double)a * 67108864.0 + (double)b) / 9007199254740992.0;
}
} // namespace mtrng

// Compile-time circuit structure
struct COps { int type[NOPS]; int pa[NOPS]; int pb[NOPS]; };
constexpr COps make_cops() {
    COps P{};
    mtrng::MT st{}; mtrng::mt_seed(st, 1234u);
    for (int i = 0; i < NOPS; i++) {
        int kind = mtrng::mt_randint(st, 4);
        if (kind == 3) {
            int c = mtrng::mt_randint(st, 8);
            int t = mtrng::mt_randint(st, 7);
            if (t >= c) t += 1;
            P.type[i] = 3; P.pa[i] = c; P.pb[i] = t;
        } else {
            int g = kind % 3;
            int w = mtrng::mt_randint(st, 8);
            (void)mtrng::mt_double(st);   // consume the angle draws
            P.type[i] = g; P.pa[i] = w; P.pb[i] = -1;
        }
    }
    return P;
}
constexpr COps COPS = make_cops();

// Runtime angle values (same MT walk; structure must match COPS)
struct Angles { float c[NOPS]; float s[NOPS]; };
static void build_angles(Angles& A) {
    mtrng::MT st; mtrng::mt_seed(st, 1234u);
    for (int i = 0; i < NOPS; i++) {
        int kind = mtrng::mt_randint(st, 4);
        if (kind == 3) {
            (void)mtrng::mt_randint(st, 8);
            (void)mtrng::mt_randint(st, 7);
            A.c[i] = 0.f; A.s[i] = 0.f;
        } else {
            (void)mtrng::mt_randint(st, 8);
            double ang = mtrng::mt_double(st) * (2.0 * M_PI);
            float th = (float)ang;            // reference casts to float32
            double half = (double)(th * 0.5f);
            A.c[i] = (float)cos(half); A.s[i] = (float)sin(half);
        }
    }
}

// ============================================================================
// Kernel A: detect sentence dtype + precompute phiq cos/sin
// ============================================================================
__global__ void k_detect(const int4* __restrict__ sent4, const float* __restrict__ phiq) {
    __shared__ int any;
    if (threadIdx.x == 0) any = 0;
    __syncthreads();
    int loc = 0;
    for (int i = threadIdx.x; i < 4096; i += blockDim.x) {
        int4 v = sent4[i];
        loc |= v.y | v.w;
    }
    if (loc) atomicOr(&any, 1);
    __syncthreads();
    if (threadIdx.x == 0) g_flag = any ? 1 : 0;
    if (threadIdx.x < 8) {
        float c, s;
        __sincosf(0.5f * phiq[threadIdx.x], &s, &c);
        g_phiq_c[threadIdx.x] = c;
        g_phiq_s[threadIdx.x] = s;
    }
}

// ============================================================================
// Kernel B: embed-gather + input projection
// ============================================================================
__global__ void k_project(const float* __restrict__ emb,
                          const float* __restrict__ Win,
                          const float* __restrict__ b_in,
                          const float* __restrict__ phi,
                          const int*   __restrict__ sent32) {
    int warp = blockIdx.x * (blockDim.x >> 5) + (threadIdx.x >> 5);
    int lane = threadIdx.x & 31;
    if (warp >= NROWS) return;
    int rr = warp;
    int tok = sent32[g_flag ? rr : 2 * rr];
    const float* xr = emb + (long)tok * EDIM;
    float x0 = xr[lane];
    float x1 = xr[32 + lane];
    const float* wrow = Win + lane * 72;
    float acc = b_in[lane] + phi[lane];
#pragma unroll
    for (int f = 0; f < 32; f++) acc = fmaf(wrow[f],      __shfl_sync(FULLM, x0, f), acc);
#pragma unroll
    for (int f = 0; f < 32; f++) acc = fmaf(wrow[32 + f], __shfl_sync(FULLM, x1, f), acc);
    g_Zx[rr * 32 + lane] = acc;
}

// ============================================================================
// Kernel C: sequential recurrence (one warp per batch element).
// Grid padded >=148 (low-grid issue-throttle workaround); dummy CTAs exit.
// ============================================================================
__device__ __forceinline__ float fast_rcp(float x) {
    float r; asm("rcp.approx.f32 %0, %1;" : "=f"(r) : "f"(x)); return r;
}

__global__ void __launch_bounds__(32, 1) k_recur(const float* __restrict__ Win,
                                                 const float* __restrict__ Wout,
                                                 const float* __restrict__ b_out) {
    int b = blockIdx.x;
    if (b >= BATCH) return;
    int lane = threadIdx.x & 31;
    int g    = lane >> 3;
    int q    = lane & 7;

    float Wh[8];
#pragma unroll
    for (int j = 0; j < 8; j++) Wh[j] = Win[lane * 72 + 64 + j];
    float Wo[8];
#pragma unroll
    for (int j = 0; j < 8; j++) Wo[j] = Wout[g * 64 + q * 8 + j];
    float bo = b_out[lane];

    float am = (g == 2) ? 2.f : 1.f;
    float aa = (g == 2) ? -1.f : 0.f;

    float h[8];
#pragma unroll
    for (int j = 0; j < 8; j++) h[j] = 0.f;
    float cst = 0.f;

    const float* Zp = g_Zx + b * 32 + lane;
    float zin = Zp[0];

    for (int s = 0; s < S_LEN; s++) {
        float znext = (s + 1 < S_LEN) ? Zp[(s + 1) * (BATCH * 32)] : 0.f;

        float za = zin, zb = 0.f;
#pragma unroll
        for (int j = 0; j < 8; j += 2) {
            za = fmaf(Wh[j],     h[j],     za);
            zb = fmaf(Wh[j + 1], h[j + 1], zb);
        }
        float p = __cosf(za + zb);

        float pg[8];
#pragma unroll
        for (int j = 0; j < 8; j++)
            pg[j] = __shfl_sync(FULLM, p, (lane & 24) + j);

        float cum = pg[0];
        float pre = fmaf(Wo[0], cum, bo);
#pragma unroll
        for (int j = 1; j < 8; j++) {
            cum *= pg[j];
            pre = fmaf(Wo[j], cum, pre);
        }

        float xx = am * pre;
        float sg = fast_rcp(1.f + __expf(-xx));
        float act = fmaf(am, sg, aa);

        float fv = __shfl_sync(FULLM, act, q);
        float iv = __shfl_sync(FULLM, act, 8 + q);
        float gv = __shfl_sync(FULLM, act, 16 + q);
        float ov = __shfl_sync(FULLM, act, 24 + q);
        cst = fmaf(fv, cst, iv * gv);
        float tc = fmaf(2.f, fast_rcp(1.f + __expf(-2.f * cst)), -1.f);
        float hval = ov * tc;

        if (lane < 8) g_hs[(s * BATCH + b) * HDIM + lane] = hval;
#pragma unroll
        for (int j = 0; j < 8; j++) h[j] = __shfl_sync(FULLM, hval, j);
        zin = znext;
    }
}

// ============================================================================
// Kernel D: quantum head — compile-time-specialized circuit.
// 256 amps: lane holds amps m = lane*8 + k. wire w <-> bit (7-w).
// bits 7..3 = lane bits (wires 0..4), bits 2..0 = intra-lane (wires 5..7).
// ============================================================================
template<int BB, bool RX>
__device__ __forceinline__ void rot_lane_t(float* ar, float* ai, float c, float s, int lane) {
    constexpr int delta = 1 << (BB - 3);
    float sgn = ((lane >> (BB - 3)) & 1) ? s : -s;   // for RY
#pragma unroll
    for (int k = 0; k < 8; k++) {
        float pr = __shfl_xor_sync(FULLM, ar[k], delta);
        float pi = __shfl_xor_sync(FULLM, ai[k], delta);
        if (RX) {
            float nr = fmaf(s, pi, c * ar[k]);
            float ni = fmaf(-s, pr, c * ai[k]);
            ar[k] = nr; ai[k] = ni;
        } else {
            ar[k] = fmaf(sgn, pr, c * ar[k]);
            ai[k] = fmaf(sgn, pi, c * ai[k]);
        }
    }
}

template<int M, bool RX>
__device__ __forceinline__ void rot_intra_tt(float* ar, float* ai, float c, float s) {
#pragma unroll
    for (int k = 0; k < 8; k++) {
        if (!(k & M)) {
            const int k1 = k | M;
            float a0r = ar[k], a0i = ai[k], a1r = ar[k1], a1i = ai[k1];
            if (RX) {
                ar[k]  = fmaf(s, a1i, c * a0r);  ai[k]  = fmaf(-s, a1r, c * a0i);
                ar[k1] = fmaf(s, a0i, c * a1r);  ai[k1] = fmaf(-s, a0r, c * a1i);
            } else {
                ar[k]  = fmaf(-s, a1r, c * a0r); ai[k]  = fmaf(-s, a1i, c * a0i);
                ar[k1] = fmaf( s, a0r, c * a1r); ai[k1] = fmaf( s, a0i, c * a1i);
            }
        }
    }
}

template<int BB>
__device__ __forceinline__ void rz_t(float* ar, float* ai, float c, float s, int lane) {
    if (BB >= 3) {
        float sg = ((lane >> (BB - 3)) & 1) ? -s : s;
#pragma unroll
        for (int k = 0; k < 8; k++) {
            float nr = fmaf(sg, ai[k], c * ar[k]);
            float ni = fmaf(-sg, ar[k], c * ai[k]);
            ar[k] = nr; ai[k] = ni;
        }
    } else {
#pragma unroll
        for (int k = 0; k < 8; k++) {
            float sg = ((k >> BB) & 1) ? -s : s;   // compile-time fold per k
            float nr = fmaf(sg, ai[k], c * ar[k]);
            float ni = fmaf(-sg, ar[k], c * ai[k]);
            ar[k] = nr; ai[k] = ni;
        }
    }
}

template<int BC, int BT>
__device__ __forceinline__ void cnot_t(float* ar, float* ai, int lane) {
    if (BC >= 3 && BT >= 3) {
        constexpr int delta = (BT >= 3) ? (1 << (BT - 3)) : 1;
        int ctrl = (lane >> (BC - 3)) & 1;
#pragma unroll
        for (int k = 0; k < 8; k++) {
            float pr = __shfl_xor_sync(FULLM, ar[k], delta);
            float pi = __shfl_xor_sync(FULLM, ai[k], delta);
            if (ctrl) { ar[k] = pr; ai[k] = pi; }
        }
    } else if (BC >= 3) {
        constexpr int M = (BT < 3) ? (1 << BT) : 1;
        bool ctrl = ((lane >> (BC - 3)) & 1) != 0;
#pragma unroll
        for (int k = 0; k < 8; k++) if (!(k & M)) {
            const int k1 = k | M;
            float t0r = ctrl ? ar[k1] : ar[k];
            float t1r = ctrl ? ar[k]  : ar[k1];
            float t0i = ctrl ? ai[k1] : ai[k];
            float t1i = ctrl ? ai[k]  : ai[k1];
            ar[k] = t0r; ar[k1] = t1r; ai[k] = t0i; ai[k1] = t1i;
        }
    } else if (BT >= 3) {
        constexpr int delta = (BT >= 3) ? (1 << (BT - 3)) : 1;
        constexpr int MC = (BC < 3) ? (1 << BC) : 1;
#pragma unroll
        for (int k = 0; k < 8; k++) if (k & MC) {
            ar[k] = __shfl_xor_sync(FULLM, ar[k], delta);
            ai[k] = __shfl_xor_sync(FULLM, ai[k], delta);
        }
    } else {
        constexpr int MC = (BC < 3) ? (1 << BC) : 1;
        constexpr int M  = (BT < 3) ? (1 << BT) : 1;
#pragma unroll
        for (int k = 0; k < 8; k++) if ((k & MC) && !(k & M)) {
            const int k1 = k | M;
            float t = ar[k]; ar[k] = ar[k1]; ar[k1] = t;
            t = ai[k]; ai[k] = ai[k1]; ai[k1] = t;   // pure register rename
        }
    }
}

template<int I>
__device__ __forceinline__ void apply_ops(float* ar, float* ai,
                                          const float* Pc, const float* Ps, int lane) {
    if constexpr (I < NOPS) {
        constexpr int ty = COPS.type[I];
        if constexpr (ty == 3) {
            cnot_t<7 - COPS.pa[I], 7 - COPS.pb[I]>(ar, ai, lane);
        } else {
            constexpr int bb = 7 - COPS.pa[I];
            const float c = Pc[I], s = Ps[I];
            if constexpr (ty == 2)      rz_t<bb>(ar, ai, c, s, lane);
            else if constexpr (bb >= 3) rot_lane_t<bb, ty == 0>(ar, ai, c, s, lane);
            else                        rot_intra_tt<(1 << bb), ty == 0>(ar, ai, c, s);
        }
        apply_ops<I + 1>(ar, ai, Pc, Ps, lane);
    }
}

template<int W>
__device__ __forceinline__ void apply_phiq(float* ar, float* ai, int lane) {
    if constexpr (W < 8) {
        float c = g_phiq_c[W];
        float s = g_phiq_s[W];
        constexpr int BB = 7 - W;
        if constexpr (BB >= 3) rot_lane_t<BB, true>(ar, ai, c, s, lane);
        else                   rot_intra_tt<(1 << BB), true>(ar, ai, c, s);
        apply_phiq<W + 1>(ar, ai, lane);
    }
}

__global__ void __launch_bounds__(256) k_head(const float* __restrict__ Whead,
                                              const float* __restrict__ b_head,
                                              float* __restrict__ out,
                                              Angles A) {
    int warp = blockIdx.x * (blockDim.x >> 5) + (threadIdx.x >> 5);
    int lane = threadIdx.x & 31;
    if (warp >= NROWS) return;
    int r  = warp;
    int sp = r >> 7;        // s'
    int bp = r & 127;       // b'
    // out[s'][b'] <- hidden at (s = b', batch = s')   (batch-major reshape algebra)
    int hoff = ((bp << 7) + sp) * HDIM;

    // ---- encode: product state from RY angles ----
    float ce = 1.f, se = 0.f;
    if (lane < 8) {
        float th = 0.5f * g_hs[hoff + lane];
        __sincosf(th, &se, &ce);
    }
    float Fl = 1.f;
#pragma unroll
    for (int w = 0; w < 5; w++) {
        float cw = __shfl_sync(FULLM, ce, w);
        float sw = __shfl_sync(FULLM, se, w);
        Fl *= ((lane >> (4 - w)) & 1) ? sw : cw;
    }
    float c5 = __shfl_sync(FULLM, ce, 5), s5v = __shfl_sync(FULLM, se, 5);
    float c6 = __shfl_sync(FULLM, ce, 6), s6v = __shfl_sync(FULLM, se, 6);
    float c7 = __shfl_sync(FULLM, ce, 7), s7v = __shfl_sync(FULLM, se, 7);
    float ar[8], ai[8];
#pragma unroll
    for (int k = 0; k < 8; k++) {
        float f = ((k & 4) ? s5v : c5) * ((k & 2) ? s6v : c6) * ((k & 1) ? s7v : c7);
        ar[k] = Fl * f; ai[k] = 0.f;
    }

    // ---- fixed random layer (fully unrolled, compile-time structure) ----
    apply_ops<0>(ar, ai, A.c, A.s, lane);

    // ---- trainable RX(phiq) on every wire (precomputed cos/sin) ----
    apply_phiq<0>(ar, ai, lane);

    // ---- measure <Z_w> ----
    float p[8];
#pragma unroll
    for (int k = 0; k < 8; k++) p[k] = fmaf(ar[k], ar[k], ai[k] * ai[k]);
    float tot = 0.f, sA = 0.f, sB = 0.f, sC = 0.f;
#pragma unroll
    for (int k = 0; k < 8; k++) {
        tot += p[k];
        sA += (k & 4) ? -p[k] : p[k];
        sB += (k & 2) ? -p[k] : p[k];
        sC += (k & 1) ? -p[k] : p[k];
    }
    // FWHT over lanes: lane L ends with sum_j (-1)^{popc(L&j)} tot_j
    float x = tot;
#pragma unroll
    for (int d = 16; d >= 1; d >>= 1) {
        float o = __shfl_xor_sync(FULLM, x, d);
        x = (lane & d) ? (o - x) : (x + o);
    }
    float z[8];
    z[0] = __shfl_sync(FULLM, x, 16);
    z[1] = __shfl_sync(FULLM, x, 8);
    z[2] = __shfl_sync(FULLM, x, 4);
    z[3] = __shfl_sync(FULLM, x, 2);
    z[4] = __shfl_sync(FULLM, x, 1);
#pragma unroll
    for (int d = 16; d >= 1; d >>= 1) {
        sA += __shfl_xor_sync(FULLM, sA, d);
        sB += __shfl_xor_sync(FULLM, sB, d);
        sC += __shfl_xor_sync(FULLM, sC, d);
    }
    z[5] = sA; z[6] = sB; z[7] = sC;

    // ---- logits + log_softmax over T=12 ----
    float lg = 0.f;
    if (lane < TDIM) {
        lg = b_head[lane];
#pragma unroll
        for (int k = 0; k < 8; k++) lg = fmaf(z[k], Whead[lane * 8 + k], lg);
    }
    float mv = (lane < TDIM) ? lg : -3.0e38f;
#pragma unroll
    for (int d = 16; d >= 1; d >>= 1) mv = fmaxf(mv, __shfl_xor_sync(FULLM, mv, d));
    float ev = (lane < TDIM) ? __expf(lg - mv) : 0.f;
#pragma unroll
    for (int d = 16; d >= 1; d >>= 1) ev += __shfl_xor_sync(FULLM, ev, d);
    if (lane < TDIM) out[r * TDIM + lane] = lg - mv - __logf(ev);
}

// ============================================================================
// Launch
// ============================================================================
extern "C" void kernel_launch(void* const* d_in, const int* in_sizes, int n_in,
                              void* d_out, int out_size) {
    (void)in_sizes; (void)n_in; (void)out_size;
    const float* emb    = (const float*)d_in[0];
    const float* Win    = (const float*)d_in[1];
    const float* b_in   = (const float*)d_in[2];
    const float* phi    = (const float*)d_in[3];
    const float* Wout   = (const float*)d_in[4];
    const float* b_out  = (const float*)d_in[5];
    const float* phiq   = (const float*)d_in[6];
    const float* Whead  = (const float*)d_in[7];
    const float* b_head = (const float*)d_in[8];
    const int*   sent32 = (const int*)d_in[9];
    float* out = (float*)d_out;

    Angles A;
    build_angles(A);   // deterministic; recomputed every call (cheap)

    k_detect<<<1, 256>>>((const int4*)sent32, phiq);
    k_project<<<NROWS / 8, 256>>>(emb, Win, b_in, phi, sent32);
    k_recur<<<256, 32>>>(Win, Wout, b_out);   // padded >=148; extra CTAs exit
    k_head<<<NROWS / 8, 256>>>(Whead, b_head, out, A);
}

// round 6
// speedup vs baseline: 1.7562x; 1.2031x over previous
#include <cuda_runtime.h>
#include <cstdint>
#include <math.h>

// Problem constants
#define S_LEN  128
#define BATCH  128
#define EDIM   64
#define HDIM   8
#define TDIM   12
#define NROWS  (S_LEN*BATCH)   // 16384
#define FULLM  0xffffffffu
#define NOPS   30

// -------------------- device scratch (no allocations allowed) ---------------
__device__ float g_Zx[NROWS * 32];    // per-(s,b) input projection (+b_in+phi), 2 MB
__device__ float g_hs[NROWS * HDIM];  // hidden states hs[s][b][h], 512 KB
__device__ int   g_flag;              // 1 => sentence buffer is int32, 0 => int64
__device__ float g_phiq_c[8], g_phiq_s[8];

// ============================================================================
// numpy-legacy MT19937 — constexpr so the circuit STRUCTURE is compile-time.
// ============================================================================
namespace mtrng {
struct MT { uint32_t key[624]; int pos; };
constexpr void mt_seed(MT& st, uint32_t s) {
    for (int i = 0; i < 624; i++) { st.key[i] = s; s = 1812433253u * (s ^ (s >> 30)) + (uint32_t)i + 1u; }
    st.pos = 624;
}
constexpr void mt_gen(MT& st) {
    int i = 0; uint32_t y = 0;
    for (i = 0; i < 624 - 397; i++) {
        y = (st.key[i] & 0x80000000u) | (st.key[i + 1] & 0x7fffffffu);
        st.key[i] = st.key[i + 397] ^ (y >> 1) ^ ((y & 1u) ? 0x9908b0dfu : 0u);
    }
    for (; i < 623; i++) {
        y = (st.key[i] & 0x80000000u) | (st.key[i + 1] & 0x7fffffffu);
        st.key[i] = st.key[i - 227] ^ (y >> 1) ^ ((y & 1u) ? 0x9908b0dfu : 0u);
    }
    y = (st.key[623] & 0x80000000u) | (st.key[0] & 0x7fffffffu);
    st.key[623] = st.key[396] ^ (y >> 1) ^ ((y & 1u) ? 0x9908b0dfu : 0u);
    st.pos = 0;
}
constexpr uint32_t mt_next(MT& st) {
    if (st.pos == 624) mt_gen(st);
    uint32_t y = st.key[st.pos++];
    y ^= y >> 11; y ^= (y << 7) & 0x9d2c5680u; y ^= (y << 15) & 0xefc60000u; y ^= y >> 18;
    return y;
}
constexpr int mt_randint(MT& st, uint32_t n) {
    uint32_t rng = n - 1u;
    uint32_t mask = rng;
    mask |= mask >> 1; mask |= mask >> 2; mask |= mask >> 4; mask |= mask >> 8; mask |= mask >> 16;
    uint32_t v = 0;
    do { v = mt_next(st) & mask; } while (v > rng);
    return (int)v;
}
constexpr double mt_double(MT& st) {
    uint32_t a = mt_next(st) >> 5, b = mt_next(st) >> 6;
    return ((double)a * 67108864.0 + (double)b) / 9007199254740992.0;
}
} // namespace mtrng

// Compile-time circuit structure
struct COps { int type[NOPS]; int pa[NOPS]; int pb[NOPS]; };
constexpr COps make_cops() {
    COps P{};
    mtrng::MT st{}; mtrng::mt_seed(st, 1234u);
    for (int i = 0; i < NOPS; i++) {
        int kind = mtrng::mt_randint(st, 4);
        if (kind == 3) {
            int c = mtrng::mt_randint(st, 8);
            int t = mtrng::mt_randint(st, 7);
            if (t >= c) t += 1;
            P.type[i] = 3; P.pa[i] = c; P.pb[i] = t;
        } else {
            int g = kind % 3;
            int w = mtrng::mt_randint(st, 8);
            (void)mtrng::mt_double(st);   // consume the angle draws
            P.type[i] = g; P.pa[i] = w; P.pb[i] = -1;
        }
    }
    return P;
}
constexpr COps COPS = make_cops();

// Runtime angle values (same MT walk; structure must match COPS)
struct Angles { float c[NOPS]; float s[NOPS]; };
static void build_angles(Angles& A) {
    mtrng::MT st; mtrng::mt_seed(st, 1234u);
    for (int i = 0; i < NOPS; i++) {
        int kind = mtrng::mt_randint(st, 4);
        if (kind == 3) {
            (void)mtrng::mt_randint(st, 8);
            (void)mtrng::mt_randint(st, 7);
            A.c[i] = 0.f; A.s[i] = 0.f;
        } else {
            (void)mtrng::mt_randint(st, 8);
            double ang = mtrng::mt_double(st) * (2.0 * M_PI);
            float th = (float)ang;            // reference casts to float32
            double half = (double)(th * 0.5f);
            A.c[i] = (float)cos(half); A.s[i] = (float)sin(half);
        }
    }
}

// ============================================================================
// Kernel A: detect sentence dtype + precompute phiq cos/sin
// ============================================================================
__global__ void k_detect(const int4* __restrict__ sent4, const float* __restrict__ phiq) {
    __shared__ int any;
    if (threadIdx.x == 0) any = 0;
    __syncthreads();
    int loc = 0;
    for (int i = threadIdx.x; i < 4096; i += blockDim.x) {
        int4 v = sent4[i];
        loc |= v.y | v.w;
    }
    if (loc) atomicOr(&any, 1);
    __syncthreads();
    if (threadIdx.x == 0) g_flag = any ? 1 : 0;
    if (threadIdx.x < 8) {
        float c, s;
        __sincosf(0.5f * phiq[threadIdx.x], &s, &c);
        g_phiq_c[threadIdx.x] = c;
        g_phiq_s[threadIdx.x] = s;
    }
}

// ============================================================================
// Kernel B: embed-gather + input projection
// ============================================================================
__global__ void k_project(const float* __restrict__ emb,
                          const float* __restrict__ Win,
                          const float* __restrict__ b_in,
                          const float* __restrict__ phi,
                          const int*   __restrict__ sent32) {
    int warp = blockIdx.x * (blockDim.x >> 5) + (threadIdx.x >> 5);
    int lane = threadIdx.x & 31;
    if (warp >= NROWS) return;
    int rr = warp;
    int tok = sent32[g_flag ? rr : 2 * rr];
    const float* xr = emb + (long)tok * EDIM;
    float x0 = xr[lane];
    float x1 = xr[32 + lane];
    const float* wrow = Win + lane * 72;
    float acc = b_in[lane] + phi[lane];
#pragma unroll
    for (int f = 0; f < 32; f++) acc = fmaf(wrow[f],      __shfl_sync(FULLM, x0, f), acc);
#pragma unroll
    for (int f = 0; f < 32; f++) acc = fmaf(wrow[32 + f], __shfl_sync(FULLM, x1, f), acc);
    g_Zx[rr * 32 + lane] = acc;
}

// ============================================================================
// Kernel C: sequential recurrence (one warp per batch element).
// Critical-path-minimized: MUFU.TANH activations, tree cumprod, 2-deep prefetch.
// ============================================================================
__device__ __forceinline__ float fast_tanh(float x) {
    float r; asm("tanh.approx.f32 %0, %1;" : "=f"(r) : "f"(x)); return r;
}

__global__ void __launch_bounds__(32, 1) k_recur(const float* __restrict__ Win,
                                                 const float* __restrict__ Wout,
                                                 const float* __restrict__ b_out) {
    int b = blockIdx.x;
    int lane = threadIdx.x & 31;
    int g    = lane >> 3;
    int q    = lane & 7;

    float Wh[8];
#pragma unroll
    for (int j = 0; j < 8; j++) Wh[j] = Win[lane * 72 + 64 + j];
    float Wo[8];
#pragma unroll
    for (int j = 0; j < 8; j++) Wo[j] = Wout[g * 64 + q * 8 + j];
    float bo = b_out[lane];

    // act = fma(aA, tanh(aB*pre), aC):
    //   sigmoid (g=0,1,3): 0.5 + 0.5*tanh(0.5*x)
    //   tanh    (g=2):     tanh(x)
    float aAB = (g == 2) ? 1.f : 0.5f;   // aA == aB
    float aC  = (g == 2) ? 0.f : 0.5f;

    float h[8];
#pragma unroll
    for (int j = 0; j < 8; j++) h[j] = 0.f;
    float cst = 0.f;

    const int BSTR = BATCH * 32;
    const float* Zp = g_Zx + b * 32 + lane;
    float zA = Zp[0];
    float zB = Zp[BSTR];

    for (int s = 0; s < S_LEN; s++) {
        // prefetch 2 steps ahead (covers L2 latency vs shortened step)
        float zC = (s + 2 < S_LEN) ? Zp[(s + 2) * BSTR] : 0.f;

        // z = zA + Wh·h   (two accumulator chains)
        float za = zA, zb = 0.f;
#pragma unroll
        for (int j = 0; j < 8; j += 2) {
            za = fmaf(Wh[j],     h[j],     za);
            zb = fmaf(Wh[j + 1], h[j + 1], zb);
        }
        float p = __cosf(za + zb);

        // gather this gate-group's 8 cos values (independent shfls)
        int base = lane & 24;
        float pg[8];
#pragma unroll
        for (int j = 0; j < 8; j++)
            pg[j] = __shfl_sync(FULLM, p, base + j);

        // depth-3 prefix-product tree
        float t01 = pg[0] * pg[1], t23 = pg[2] * pg[3];
        float t45 = pg[4] * pg[5], t67 = pg[6] * pg[7];
        float q03 = t01 * t23;
        float P0 = pg[0];
        float P1 = t01;
        float P2 = t01 * pg[2];
        float P3 = q03;
        float P4 = q03 * pg[4];
        float P5 = q03 * t45;
        float P6 = P5 * pg[6];
        float P7 = q03 * (t45 * t67);

        // two-chain Wout dot
        float prA = fmaf(Wo[0], P0, bo);
        float prB = Wo[1] * P1;
        prA = fmaf(Wo[2], P2, prA);
        prB = fmaf(Wo[3], P3, prB);
        prA = fmaf(Wo[4], P4, prA);
        prB = fmaf(Wo[5], P5, prB);
        prA = fmaf(Wo[6], P6, prA);
        prB = fmaf(Wo[7], P7, prB);
        float pre = prA + prB;

        // activation via single MUFU.TANH
        float act = fmaf(aAB, fast_tanh(aAB * pre), aC);

        float fv = __shfl_sync(FULLM, act, q);
        float iv = __shfl_sync(FULLM, act, 8 + q);
        float gv = __shfl_sync(FULLM, act, 16 + q);
        float ov = __shfl_sync(FULLM, act, 24 + q);
        cst = fmaf(fv, cst, iv * gv);
        float hval = ov * fast_tanh(cst);

        if (lane < 8) g_hs[(s * BATCH + b) * HDIM + lane] = hval;
#pragma unroll
        for (int j = 0; j < 8; j++) h[j] = __shfl_sync(FULLM, hval, j);
        zA = zB; zB = zC;
    }
}

// ============================================================================
// Kernel D: quantum head — compile-time-specialized circuit.
// 256 amps: lane holds amps m = lane*8 + k. wire w <-> bit (7-w).
// bits 7..3 = lane bits (wires 0..4), bits 2..0 = intra-lane (wires 5..7).
// ============================================================================
template<int BB, bool RX>
__device__ __forceinline__ void rot_lane_t(float* ar, float* ai, float c, float s, int lane) {
    constexpr int delta = 1 << (BB - 3);
    float sgn = ((lane >> (BB - 3)) & 1) ? s : -s;   // for RY
#pragma unroll
    for (int k = 0; k < 8; k++) {
        float pr = __shfl_xor_sync(FULLM, ar[k], delta);
        float pi = __shfl_xor_sync(FULLM, ai[k], delta);
        if (RX) {
            float nr = fmaf(s, pi, c * ar[k]);
            float ni = fmaf(-s, pr, c * ai[k]);
            ar[k] = nr; ai[k] = ni;
        } else {
            ar[k] = fmaf(sgn, pr, c * ar[k]);
            ai[k] = fmaf(sgn, pi, c * ai[k]);
        }
    }
}

template<int M, bool RX>
__device__ __forceinline__ void rot_intra_tt(float* ar, float* ai, float c, float s) {
#pragma unroll
    for (int k = 0; k < 8; k++) {
        if (!(k & M)) {
            const int k1 = k | M;
            float a0r = ar[k], a0i = ai[k], a1r = ar[k1], a1i = ai[k1];
            if (RX) {
                ar[k]  = fmaf(s, a1i, c * a0r);  ai[k]  = fmaf(-s, a1r, c * a0i);
                ar[k1] = fmaf(s, a0i, c * a1r);  ai[k1] = fmaf(-s, a0r, c * a1i);
            } else {
                ar[k]  = fmaf(-s, a1r, c * a0r); ai[k]  = fmaf(-s, a1i, c * a0i);
                ar[k1] = fmaf( s, a0r, c * a1r); ai[k1] = fmaf( s, a0i, c * a1i);
            }
        }
    }
}

template<int BB>
__device__ __forceinline__ void rz_t(float* ar, float* ai, float c, float s, int lane) {
    if (BB >= 3) {
        float sg = ((lane >> (BB - 3)) & 1) ? -s : s;
#pragma unroll
        for (int k = 0; k < 8; k++) {
            float nr = fmaf(sg, ai[k], c * ar[k]);
            float ni = fmaf(-sg, ar[k], c * ai[k]);
            ar[k] = nr; ai[k] = ni;
        }
    } else {
#pragma unroll
        for (int k = 0; k < 8; k++) {
            float sg = ((k >> BB) & 1) ? -s : s;   // compile-time fold per k
            float nr = fmaf(sg, ai[k], c * ar[k]);
            float ni = fmaf(-sg, ar[k], c * ai[k]);
            ar[k] = nr; ai[k] = ni;
        }
    }
}

template<int BC, int BT>
__device__ __forceinline__ void cnot_t(float* ar, float* ai, int lane) {
    if (BC >= 3 && BT >= 3) {
        constexpr int delta = (BT >= 3) ? (1 << (BT - 3)) : 1;
        int ctrl = (lane >> (BC - 3)) & 1;
#pragma unroll
        for (int k = 0; k < 8; k++) {
            float pr = __shfl_xor_sync(FULLM, ar[k], delta);
            float pi = __shfl_xor_sync(FULLM, ai[k], delta);
            if (ctrl) { ar[k] = pr; ai[k] = pi; }
        }
    } else if (BC >= 3) {
        constexpr int M = (BT < 3) ? (1 << BT) : 1;
        bool ctrl = ((lane >> (BC - 3)) & 1) != 0;
#pragma unroll
        for (int k = 0; k < 8; k++) if (!(k & M)) {
            const int k1 = k | M;
            float t0r = ctrl ? ar[k1] : ar[k];
            float t1r = ctrl ? ar[k]  : ar[k1];
            float t0i = ctrl ? ai[k1] : ai[k];
            float t1i = ctrl ? ai[k]  : ai[k1];
            ar[k] = t0r; ar[k1] = t1r; ai[k] = t0i; ai[k1] = t1i;
        }
    } else if (BT >= 3) {
        constexpr int delta = (BT >= 3) ? (1 << (BT - 3)) : 1;
        constexpr int MC = (BC < 3) ? (1 << BC) : 1;
#pragma unroll
        for (int k = 0; k < 8; k++) if (k & MC) {
            ar[k] = __shfl_xor_sync(FULLM, ar[k], delta);
            ai[k] = __shfl_xor_sync(FULLM, ai[k], delta);
        }
    } else {
        constexpr int MC = (BC < 3) ? (1 << BC) : 1;
        constexpr int M  = (BT < 3) ? (1 << BT) : 1;
#pragma unroll
        for (int k = 0; k < 8; k++) if ((k & MC) && !(k & M)) {
            const int k1 = k | M;
            float t = ar[k]; ar[k] = ar[k1]; ar[k1] = t;
            t = ai[k]; ai[k] = ai[k1]; ai[k1] = t;   // pure register rename
        }
    }
}

template<int I>
__device__ __forceinline__ void apply_ops(float* ar, float* ai,
                                          const float* Pc, const float* Ps, int lane) {
    if constexpr (I < NOPS) {
        constexpr int ty = COPS.type[I];
        if constexpr (ty == 3) {
            cnot_t<7 - COPS.pa[I], 7 - COPS.pb[I]>(ar, ai, lane);
        } else {
            constexpr int bb = 7 - COPS.pa[I];
            const float c = Pc[I], s = Ps[I];
            if constexpr (ty == 2)      rz_t<bb>(ar, ai, c, s, lane);
            else if constexpr (bb >= 3) rot_lane_t<bb, ty == 0>(ar, ai, c, s, lane);
            else                        rot_intra_tt<(1 << bb), ty == 0>(ar, ai, c, s);
        }
        apply_ops<I + 1>(ar, ai, Pc, Ps, lane);
    }
}

template<int W>
__device__ __forceinline__ void apply_phiq(float* ar, float* ai, int lane) {
    if constexpr (W < 8) {
        float c = g_phiq_c[W];
        float s = g_phiq_s[W];
        constexpr int BB = 7 - W;
        if constexpr (BB >= 3) rot_lane_t<BB, true>(ar, ai, c, s, lane);
        else                   rot_intra_tt<(1 << BB), true>(ar, ai, c, s);
        apply_phiq<W + 1>(ar, ai, lane);
    }
}

__global__ void __launch_bounds__(256) k_head(const float* __restrict__ Whead,
                                              const float* __restrict__ b_head,
                                              float* __restrict__ out,
                                              Angles A) {
    int warp = blockIdx.x * (blockDim.x >> 5) + (threadIdx.x >> 5);
    int lane = threadIdx.x & 31;
    if (warp >= NROWS) return;
    int r  = warp;
    int sp = r >> 7;        // s'
    int bp = r & 127;       // b'
    // out[s'][b'] <- hidden at (s = b', batch = s')   (batch-major reshape algebra)
    int hoff = ((bp << 7) + sp) * HDIM;

    // ---- encode: product state from RY angles ----
    float ce = 1.f, se = 0.f;
    if (lane < 8) {
        float th = 0.5f * g_hs[hoff + lane];
        __sincosf(th, &se, &ce);
    }
    float Fl = 1.f;
#pragma unroll
    for (int w = 0; w < 5; w++) {
        float cw = __shfl_sync(FULLM, ce, w);
        float sw = __shfl_sync(FULLM, se, w);
        Fl *= ((lane >> (4 - w)) & 1) ? sw : cw;
    }
    float c5 = __shfl_sync(FULLM, ce, 5), s5v = __shfl_sync(FULLM, se, 5);
    float c6 = __shfl_sync(FULLM, ce, 6), s6v = __shfl_sync(FULLM, se, 6);
    float c7 = __shfl_sync(FULLM, ce, 7), s7v = __shfl_sync(FULLM, se, 7);
    float ar[8], ai[8];
#pragma unroll
    for (int k = 0; k < 8; k++) {
        float f = ((k & 4) ? s5v : c5) * ((k & 2) ? s6v : c6) * ((k & 1) ? s7v : c7);
        ar[k] = Fl * f; ai[k] = 0.f;
    }

    // ---- fixed random layer (fully unrolled, compile-time structure) ----
    apply_ops<0>(ar, ai, A.c, A.s, lane);

    // ---- trainable RX(phiq) on every wire (precomputed cos/sin) ----
    apply_phiq<0>(ar, ai, lane);

    // ---- measure <Z_w> ----
    float p[8];
#pragma unroll
    for (int k = 0; k < 8; k++) p[k] = fmaf(ar[k], ar[k], ai[k] * ai[k]);
    float tot = 0.f, sA = 0.f, sB = 0.f, sC = 0.f;
#pragma unroll
    for (int k = 0; k < 8; k++) {
        tot += p[k];
        sA += (k & 4) ? -p[k] : p[k];
        sB += (k & 2) ? -p[k] : p[k];
        sC += (k & 1) ? -p[k] : p[k];
    }
    // FWHT over lanes: lane L ends with sum_j (-1)^{popc(L&j)} tot_j
    float x = tot;
#pragma unroll
    for (int d = 16; d >= 1; d >>= 1) {
        float o = __shfl_xor_sync(FULLM, x, d);
        x = (lane & d) ? (o - x) : (x + o);
    }
    float z[8];
    z[0] = __shfl_sync(FULLM, x, 16);
    z[1] = __shfl_sync(FULLM, x, 8);
    z[2] = __shfl_sync(FULLM, x, 4);
    z[3] = __shfl_sync(FULLM, x, 2);
    z[4] = __shfl_sync(FULLM, x, 1);
#pragma unroll
    for (int d = 16; d >= 1; d >>= 1) {
        sA += __shfl_xor_sync(FULLM, sA, d);
        sB += __shfl_xor_sync(FULLM, sB, d);
        sC += __shfl_xor_sync(FULLM, sC, d);
    }
    z[5] = sA; z[6] = sB; z[7] = sC;

    // ---- logits + log_softmax over T=12 ----
    float lg = 0.f;
    if (lane < TDIM) {
        lg = b_head[lane];
#pragma unroll
        for (int k = 0; k < 8; k++) lg = fmaf(z[k], Whead[lane * 8 + k], lg);
    }
    float mv = (lane < TDIM) ? lg : -3.0e38f;
#pragma unroll
    for (int d = 16; d >= 1; d >>= 1) mv = fmaxf(mv, __shfl_xor_sync(FULLM, mv, d));
    float ev = (lane < TDIM) ? __expf(lg - mv) : 0.f;
#pragma unroll
    for (int d = 16; d >= 1; d >>= 1) ev += __shfl_xor_sync(FULLM, ev, d);
    if (lane < TDIM) out[r * TDIM + lane] = lg - mv - __logf(ev);
}

// ============================================================================
// Launch
// ============================================================================
extern "C" void kernel_launch(void* const* d_in, const int* in_sizes, int n_in,
                              void* d_out, int out_size) {
    (void)in_sizes; (void)n_in; (void)out_size;
    const float* emb    = (const float*)d_in[0];
    const float* Win    = (const float*)d_in[1];
    const float* b_in   = (const float*)d_in[2];
    const float* phi    = (const float*)d_in[3];
    const float* Wout   = (const float*)d_in[4];
    const float* b_out  = (const float*)d_in[5];
    const float* phiq   = (const float*)d_in[6];
    const float* Whead  = (const float*)d_in[7];
    const float* b_head = (const float*)d_in[8];
    const int*   sent32 = (const int*)d_in[9];
    float* out = (float*)d_out;

    Angles A;
    build_angles(A);   // deterministic; recomputed every call (cheap)

    k_detect<<<1, 256>>>((const int4*)sent32, phiq);
    k_project<<<NROWS / 8, 256>>>(emb, Win, b_in, phi, sent32);
    k_recur<<<BATCH, 32>>>(Win, Wout, b_out);
    k_head<<<NROWS / 8, 256>>>(Whead, b_head, out, A);
}

// round 8
// speedup vs baseline: 1.7810x; 1.0141x over previous
#include <cuda_runtime.h>
#include <cstdint>
#include <math.h>

// Problem constants
#define S_LEN  128
#define BATCH  128
#define EDIM   64
#define HDIM   8
#define TDIM   12
#define NROWS  (S_LEN*BATCH)   // 16384
#define FULLM  0xffffffffu
#define NOPS   30

// -------------------- device scratch (no allocations allowed) ---------------
__device__ float g_Zx[NROWS * 32];    // per-(s,b) input projection (+b_in+phi), 2 MB
__device__ float g_hs[NROWS * HDIM];  // hidden states hs[s][b][h], 512 KB
__device__ int   g_flag;              // 1 => sentence buffer is int32, 0 => int64
__device__ float g_phiq_c[8], g_phiq_s[8];

// ============================================================================
// numpy-legacy MT19937 — constexpr so the circuit STRUCTURE is compile-time.
// ============================================================================
namespace mtrng {
struct MT { uint32_t key[624]; int pos; };
constexpr void mt_seed(MT& st, uint32_t s) {
    for (int i = 0; i < 624; i++) { st.key[i] = s; s = 1812433253u * (s ^ (s >> 30)) + (uint32_t)i + 1u; }
    st.pos = 624;
}
constexpr void mt_gen(MT& st) {
    int i = 0; uint32_t y = 0;
    for (i = 0; i < 624 - 397; i++) {
        y = (st.key[i] & 0x80000000u) | (st.key[i + 1] & 0x7fffffffu);
        st.key[i] = st.key[i + 397] ^ (y >> 1) ^ ((y & 1u) ? 0x9908b0dfu : 0u);
    }
    for (; i < 623; i++) {
        y = (st.key[i] & 0x80000000u) | (st.key[i + 1] & 0x7fffffffu);
        st.key[i] = st.key[i - 227] ^ (y >> 1) ^ ((y & 1u) ? 0x9908b0dfu : 0u);
    }
    y = (st.key[623] & 0x80000000u) | (st.key[0] & 0x7fffffffu);
    st.key[623] = st.key[396] ^ (y >> 1) ^ ((y & 1u) ? 0x9908b0dfu : 0u);
    st.pos = 0;
}
constexpr uint32_t mt_next(MT& st) {
    if (st.pos == 624) mt_gen(st);
    uint32_t y = st.key[st.pos++];
    y ^= y >> 11; y ^= (y << 7) & 0x9d2c5680u; y ^= (y << 15) & 0xefc60000u; y ^= y >> 18;
    return y;
}
constexpr int mt_randint(MT& st, uint32_t n) {
    uint32_t rng = n - 1u;
    uint32_t mask = rng;
    mask |= mask >> 1; mask |= mask >> 2; mask |= mask >> 4; mask |= mask >> 8; mask |= mask >> 16;
    uint32_t v = 0;
    do { v = mt_next(st) & mask; } while (v > rng);
    return (int)v;
}
constexpr double mt_double(MT& st) {
    uint32_t a = mt_next(st) >> 5, b = mt_next(st) >> 6;
    return ((double)a * 67108864.0 + (double)b) / 9007199254740992.0;
}
} // namespace mtrng

// Compile-time circuit structure
struct COps { int type[NOPS]; int pa[NOPS]; int pb[NOPS]; };
constexpr COps make_cops() {
    COps P{};
    mtrng::MT st{}; mtrng::mt_seed(st, 1234u);
    for (int i = 0; i < NOPS; i++) {
        int kind = mtrng::mt_randint(st, 4);
        if (kind == 3) {
            int c = mtrng::mt_randint(st, 8);
            int t = mtrng::mt_randint(st, 7);
            if (t >= c) t += 1;
            P.type[i] = 3; P.pa[i] = c; P.pb[i] = t;
        } else {
            int g = kind % 3;
            int w = mtrng::mt_randint(st, 8);
            (void)mtrng::mt_double(st);   // consume the angle draws
            P.type[i] = g; P.pa[i] = w; P.pb[i] = -1;
        }
    }
    return P;
}
constexpr COps COPS = make_cops();

// Runtime angle values (same MT walk; structure must match COPS)
struct Angles { float c[NOPS]; float s[NOPS]; };
static void build_angles(Angles& A) {
    mtrng::MT st; mtrng::mt_seed(st, 1234u);
    for (int i = 0; i < NOPS; i++) {
        int kind = mtrng::mt_randint(st, 4);
        if (kind == 3) {
            (void)mtrng::mt_randint(st, 8);
            (void)mtrng::mt_randint(st, 7);
            A.c[i] = 0.f; A.s[i] = 0.f;
        } else {
            (void)mtrng::mt_randint(st, 8);
            double ang = mtrng::mt_double(st) * (2.0 * M_PI);
            float th = (float)ang;            // reference casts to float32
            double half = (double)(th * 0.5f);
            A.c[i] = (float)cos(half); A.s[i] = (float)sin(half);
        }
    }
}

// ============================================================================
// Kernel A: detect sentence dtype + precompute phiq cos/sin
// ============================================================================
__global__ void k_detect(const int4* __restrict__ sent4, const float* __restrict__ phiq) {
    __shared__ int any;
    if (threadIdx.x == 0) any = 0;
    __syncthreads();
    int loc = 0;
    for (int i = threadIdx.x; i < 4096; i += blockDim.x) {
        int4 v = sent4[i];
        loc |= v.y | v.w;
    }
    if (loc) atomicOr(&any, 1);
    __syncthreads();
    if (threadIdx.x == 0) g_flag = any ? 1 : 0;
    if (threadIdx.x < 8) {
        float c, s;
        __sincosf(0.5f * phiq[threadIdx.x], &s, &c);
        g_phiq_c[threadIdx.x] = c;
        g_phiq_s[threadIdx.x] = s;
    }
}

// ============================================================================
// Kernel B: embed-gather + input projection
// ============================================================================
__global__ void k_project(const float* __restrict__ emb,
                          const float* __restrict__ Win,
                          const float* __restrict__ b_in,
                          const float* __restrict__ phi,
                          const int*   __restrict__ sent32) {
    int warp = blockIdx.x * (blockDim.x >> 5) + (threadIdx.x >> 5);
    int lane = threadIdx.x & 31;
    if (warp >= NROWS) return;
    int rr = warp;
    int tok = sent32[g_flag ? rr : 2 * rr];
    const float* xr = emb + (long)tok * EDIM;
    float x0 = xr[lane];
    float x1 = xr[32 + lane];
    const float* wrow = Win + lane * 72;
    float acc = b_in[lane] + phi[lane];
#pragma unroll
    for (int f = 0; f < 32; f++) acc = fmaf(wrow[f],      __shfl_sync(FULLM, x0, f), acc);
#pragma unroll
    for (int f = 0; f < 32; f++) acc = fmaf(wrow[32 + f], __shfl_sync(FULLM, x1, f), acc);
    g_Zx[rr * 32 + lane] = acc;
}

// ============================================================================
// Kernel C: sequential recurrence (one warp per batch element).
// Cross-lane communication via SHARED MEMORY (LDS broadcast) instead of SHFL:
// 3 STS + 8 LDS + 3 syncwarp per step replaces 20 SHFLs.
// ============================================================================
__device__ __forceinline__ float fast_tanh(float x) {
    float r; asm("tanh.approx.f32 %0, %1;" : "=f"(r) : "f"(x)); return r;
}

__global__ void __launch_bounds__(32, 1) k_recur(const float* __restrict__ Win,
                                                 const float* __restrict__ Wout,
                                                 const float* __restrict__ b_out) {
    __shared__ __align__(16) float sp[32];    // per-lane cos values
    __shared__ __align__(16) float sact[32];  // per-lane activations
    __shared__ __align__(16) float sh[8];     // hidden vector

    int b = blockIdx.x;
    int lane = threadIdx.x & 31;
    int g    = lane >> 3;
    int q    = lane & 7;
    int base = lane & 24;

    float Wh[8];
#pragma unroll
    for (int j = 0; j < 8; j++) Wh[j] = Win[lane * 72 + 64 + j];
    float Wo[8];
#pragma unroll
    for (int j = 0; j < 8; j++) Wo[j] = Wout[g * 64 + q * 8 + j];
    float bo = b_out[lane];

    // act = fma(aA, tanh(aB*pre), aC):
    //   sigmoid (g=0,1,3): 0.5 + 0.5*tanh(0.5*x);  tanh (g=2): tanh(x)
    float aAB = (g == 2) ? 1.f : 0.5f;
    float aC  = (g == 2) ? 0.f : 0.5f;

    float h[8];
#pragma unroll
    for (int j = 0; j < 8; j++) h[j] = 0.f;
    float cst = 0.f;

    const int BSTR = BATCH * 32;
    const float* Zp = g_Zx + b * 32 + lane;
    float zA = Zp[0];
    float zB = Zp[BSTR];

#pragma unroll 2
    for (int s = 0; s < S_LEN; s++) {
        // prefetch 2 steps ahead (covers L2 latency)
        float zC = (s + 2 < S_LEN) ? Zp[(s + 2) * BSTR] : 0.f;

        // z = zA + Wh·h   (two accumulator chains)
        float za = zA, zb = 0.f;
#pragma unroll
        for (int j = 0; j < 8; j += 2) {
            za = fmaf(Wh[j],     h[j],     za);
            zb = fmaf(Wh[j + 1], h[j + 1], zb);
        }
        float p = __cosf(za + zb);

        // ---- phase 1: share cos values via smem ----
        sp[lane] = p;
        __syncwarp();
        float4 pa = *reinterpret_cast<const float4*>(sp + base);      // broadcast, no conflicts
        float4 pb = *reinterpret_cast<const float4*>(sp + base + 4);

        // depth-3 prefix-product tree
        float t01 = pa.x * pa.y, t23 = pa.z * pa.w;
        float t45 = pb.x * pb.y, t67 = pb.z * pb.w;
        float q03 = t01 * t23;
        float P0 = pa.x;
        float P1 = t01;
        float P2 = t01 * pa.z;
        float P3 = q03;
        float P4 = q03 * pb.x;
        float P5 = q03 * t45;
        float P6 = P5 * pb.z;
        float P7 = q03 * (t45 * t67);

        // two-chain Wout dot
        float prA = fmaf(Wo[0], P0, bo);
        float prB = Wo[1] * P1;
        prA = fmaf(Wo[2], P2, prA);
        prB = fmaf(Wo[3], P3, prB);
        prA = fmaf(Wo[4], P4, prA);
        prB = fmaf(Wo[5], P5, prB);
        prA = fmaf(Wo[6], P6, prA);
        prB = fmaf(Wo[7], P7, prB);
        float pre = prA + prB;

        // activation via single MUFU.TANH
        float act = fmaf(aAB, fast_tanh(aAB * pre), aC);

        // ---- phase 2: share activations via smem ----
        sact[lane] = act;
        __syncwarp();
        float fv = sact[q];          // 8 distinct addrs, 4-way broadcast
        float iv = sact[8 + q];
        float gv = sact[16 + q];
        float ov = sact[24 + q];

        cst = fmaf(fv, cst, iv * gv);
        float hval = ov * fast_tanh(cst);

        // ---- phase 3: share hidden vector via smem ----
        if (lane < 8) {
            sh[lane] = hval;
            g_hs[(s * BATCH + b) * HDIM + lane] = hval;
        }
        __syncwarp();
        float4 h0 = *reinterpret_cast<const float4*>(sh);      // pure broadcast
        float4 h1 = *reinterpret_cast<const float4*>(sh + 4);
        h[0] = h0.x; h[1] = h0.y; h[2] = h0.z; h[3] = h0.w;
        h[4] = h1.x; h[5] = h1.y; h[6] = h1.z; h[7] = h1.w;

        zA = zB; zB = zC;
    }
}

// ============================================================================
// Kernel D: quantum head — compile-time-specialized circuit.
// 256 amps: lane holds amps m = lane*8 + k. wire w <-> bit (7-w).
// bits 7..3 = lane bits (wires 0..4), bits 2..0 = intra-lane (wires 5..7).
// ============================================================================
template<int BB, bool RX>
__device__ __forceinline__ void rot_lane_t(float* ar, float* ai, float c, float s, int lane) {
    constexpr int delta = 1 << (BB - 3);
    float sgn = ((lane >> (BB - 3)) & 1) ? s : -s;   // for RY
#pragma unroll
    for (int k = 0; k < 8; k++) {
        float pr = __shfl_xor_sync(FULLM, ar[k], delta);
        float pi = __shfl_xor_sync(FULLM, ai[k], delta);
        if (RX) {
            float nr = fmaf(s, pi, c * ar[k]);
            float ni = fmaf(-s, pr, c * ai[k]);
            ar[k] = nr; ai[k] = ni;
        } else {
            ar[k] = fmaf(sgn, pr, c * ar[k]);
            ai[k] = fmaf(sgn, pi, c * ai[k]);
        }
    }
}

template<int M, bool RX>
__device__ __forceinline__ void rot_intra_tt(float* ar, float* ai, float c, float s) {
#pragma unroll
    for (int k = 0; k < 8; k++) {
        if (!(k & M)) {
            const int k1 = k | M;
            float a0r = ar[k], a0i = ai[k], a1r = ar[k1], a1i = ai[k1];
            if (RX) {
                ar[k]  = fmaf(s, a1i, c * a0r);  ai[k]  = fmaf(-s, a1r, c * a0i);
                ar[k1] = fmaf(s, a0i, c * a1r);  ai[k1] = fmaf(-s, a0r, c * a1i);
            } else {
                ar[k]  = fmaf(-s, a1r, c * a0r); ai[k]  = fmaf(-s, a1i, c * a0i);
                ar[k1] = fmaf( s, a0r, c * a1r); ai[k1] = fmaf( s, a0i, c * a1i);
            }
        }
    }
}

template<int BB>
__device__ __forceinline__ void rz_t(float* ar, float* ai, float c, float s, int lane) {
    if (BB >= 3) {
        float sg = ((lane >> (BB - 3)) & 1) ? -s : s;
#pragma unroll
        for (int k = 0; k < 8; k++) {
            float nr = fmaf(sg, ai[k], c * ar[k]);
            float ni = fmaf(-sg, ar[k], c * ai[k]);
            ar[k] = nr; ai[k] = ni;
        }
    } else {
#pragma unroll
        for (int k = 0; k < 8; k++) {
            float sg = ((k >> BB) & 1) ? -s : s;   // compile-time fold per k
            float nr = fmaf(sg, ai[k], c * ar[k]);
            float ni = fmaf(-sg, ar[k], c * ai[k]);
            ar[k] = nr; ai[k] = ni;
        }
    }
}

template<int BC, int BT>
__device__ __forceinline__ void cnot_t(float* ar, float* ai, int lane) {
    if (BC >= 3 && BT >= 3) {
        constexpr int delta = (BT >= 3) ? (1 << (BT - 3)) : 1;
        int ctrl = (lane >> (BC - 3)) & 1;
#pragma unroll
        for (int k = 0; k < 8; k++) {
            float pr = __shfl_xor_sync(FULLM, ar[k], delta);
            float pi = __shfl_xor_sync(FULLM, ai[k], delta);
            if (ctrl) { ar[k] = pr; ai[k] = pi; }
        }
    } else if (BC >= 3) {
        constexpr int M = (BT < 3) ? (1 << BT) : 1;
        bool ctrl = ((lane >> (BC - 3)) & 1) != 0;
#pragma unroll
        for (int k = 0; k < 8; k++) if (!(k & M)) {
            const int k1 = k | M;
            float t0r = ctrl ? ar[k1] : ar[k];
            float t1r = ctrl ? ar[k]  : ar[k1];
            float t0i = ctrl ? ai[k1] : ai[k];
            float t1i = ctrl ? ai[k]  : ai[k1];
            ar[k] = t0r; ar[k1] = t1r; ai[k] = t0i; ai[k1] = t1i;
        }
    } else if (BT >= 3) {
        constexpr int delta = (BT >= 3) ? (1 << (BT - 3)) : 1;
        constexpr int MC = (BC < 3) ? (1 << BC) : 1;
#pragma unroll
        for (int k = 0; k < 8; k++) if (k & MC) {
            ar[k] = __shfl_xor_sync(FULLM, ar[k], delta);
            ai[k] = __shfl_xor_sync(FULLM, ai[k], delta);
        }
    } else {
        constexpr int MC = (BC < 3) ? (1 << BC) : 1;
        constexpr int M  = (BT < 3) ? (1 << BT) : 1;
#pragma unroll
        for (int k = 0; k < 8; k++) if ((k & MC) && !(k & M)) {
            const int k1 = k | M;
            float t = ar[k]; ar[k] = ar[k1]; ar[k1] = t;
            t = ai[k]; ai[k] = ai[k1]; ai[k1] = t;   // pure register rename
        }
    }
}

template<int I>
__device__ __forceinline__ void apply_ops(float* ar, float* ai,
                                          const float* Pc, const float* Ps, int lane) {
    if constexpr (I < NOPS) {
        constexpr int ty = COPS.type[I];
        if constexpr (ty == 3) {
            cnot_t<7 - COPS.pa[I], 7 - COPS.pb[I]>(ar, ai, lane);
        } else {
            constexpr int bb = 7 - COPS.pa[I];
            const float c = Pc[I], s = Ps[I];
            if constexpr (ty == 2)      rz_t<bb>(ar, ai, c, s, lane);
            else if constexpr (bb >= 3) rot_lane_t<bb, ty == 0>(ar, ai, c, s, lane);
            else                        rot_intra_tt<(1 << bb), ty == 0>(ar, ai, c, s);
        }
        apply_ops<I + 1>(ar, ai, Pc, Ps, lane);
    }
}

template<int W>
__device__ __forceinline__ void apply_phiq(float* ar, float* ai, int lane) {
    if constexpr (W < 8) {
        float c = g_phiq_c[W];
        float s = g_phiq_s[W];
        constexpr int BB = 7 - W;
        if constexpr (BB >= 3) rot_lane_t<BB, true>(ar, ai, c, s, lane);
        else                   rot_intra_tt<(1 << BB), true>(ar, ai, c, s);
        apply_phiq<W + 1>(ar, ai, lane);
    }
}

__global__ void __launch_bounds__(256) k_head(const float* __restrict__ Whead,
                                              const float* __restrict__ b_head,
                                              float* __restrict__ out,
                                              Angles A) {
    int warp = blockIdx.x * (blockDim.x >> 5) + (threadIdx.x >> 5);
    int lane = threadIdx.x & 31;
    if (warp >= NROWS) return;
    int r  = warp;
    int sp = r >> 7;        // s'
    int bp = r & 127;       // b'
    // out[s'][b'] <- hidden at (s = b', batch = s')   (batch-major reshape algebra)
    int hoff = ((bp << 7) + sp) * HDIM;

    // ---- encode: product state from RY angles ----
    float ce = 1.f, se = 0.f;
    if (lane < 8) {
        float th = 0.5f * g_hs[hoff + lane];
        __sincosf(th, &se, &ce);
    }
    float Fl = 1.f;
#pragma unroll
    for (int w = 0; w < 5; w++) {
        float cw = __shfl_sync(FULLM, ce, w);
        float sw = __shfl_sync(FULLM, se, w);
        Fl *= ((lane >> (4 - w)) & 1) ? sw : cw;
    }
    float c5 = __shfl_sync(FULLM, ce, 5), s5v = __shfl_sync(FULLM, se, 5);
    float c6 = __shfl_sync(FULLM, ce, 6), s6v = __shfl_sync(FULLM, se, 6);
    float c7 = __shfl_sync(FULLM, ce, 7), s7v = __shfl_sync(FULLM, se, 7);
    float ar[8], ai[8];
#pragma unroll
    for (int k = 0; k < 8; k++) {
        float f = ((k & 4) ? s5v : c5) * ((k & 2) ? s6v : c6) * ((k & 1) ? s7v : c7);
        ar[k] = Fl * f; ai[k] = 0.f;
    }

    // ---- fixed random layer (fully unrolled, compile-time structure) ----
    apply_ops<0>(ar, ai, A.c, A.s, lane);

    // ---- trainable RX(phiq) on every wire (precomputed cos/sin) ----
    apply_phiq<0>(ar, ai, lane);

    // ---- measure <Z_w> ----
    float p[8];
#pragma unroll
    for (int k = 0; k < 8; k++) p[k] = fmaf(ar[k], ar[k], ai[k] * ai[k]);
    float tot = 0.f, sA = 0.f, sB = 0.f, sC = 0.f;
#pragma unroll
    for (int k = 0; k < 8; k++) {
        tot += p[k];
        sA += (k & 4) ? -p[k] : p[k];
        sB += (k & 2) ? -p[k] : p[k];
        sC += (k & 1) ? -p[k] : p[k];
    }
    // FWHT over lanes: lane L ends with sum_j (-1)^{popc(L&j)} tot_j
    float x = tot;
#pragma unroll
    for (int d = 16; d >= 1; d >>= 1) {
        float o = __shfl_xor_sync(FULLM, x, d);
        x = (lane & d) ? (o - x) : (x + o);
    }
    float z[8];
    z[0] = __shfl_sync(FULLM, x, 16);
    z[1] = __shfl_sync(FULLM, x, 8);
    z[2] = __shfl_sync(FULLM, x, 4);
    z[3] = __shfl_sync(FULLM, x, 2);
    z[4] = __shfl_sync(FULLM, x, 1);
#pragma unroll
    for (int d = 16; d >= 1; d >>= 1) {
        sA += __shfl_xor_sync(FULLM, sA, d);
        sB += __shfl_xor_sync(FULLM, sB, d);
        sC += __shfl_xor_sync(FULLM, sC, d);
    }
    z[5] = sA; z[6] = sB; z[7] = sC;

    // ---- logits + log_softmax over T=12 ----
    float lg = 0.f;
    if (lane < TDIM) {
        lg = b_head[lane];
#pragma unroll
        for (int k = 0; k < 8; k++) lg = fmaf(z[k], Whead[lane * 8 + k], lg);
    }
    float mv = (lane < TDIM) ? lg : -3.0e38f;
#pragma unroll
    for (int d = 16; d >= 1; d >>= 1) mv = fmaxf(mv, __shfl_xor_sync(FULLM, mv, d));
    float ev = (lane < TDIM) ? __expf(lg - mv) : 0.f;
#pragma unroll
    for (int d = 16; d >= 1; d >>= 1) ev += __shfl_xor_sync(FULLM, ev, d);
    if (lane < TDIM) out[r * TDIM + lane] = lg - mv - __logf(ev);
}

// ============================================================================
// Launch
// ============================================================================
extern "C" void kernel_launch(void* const* d_in, const int* in_sizes, int n_in,
                              void* d_out, int out_size) {
    (void)in_sizes; (void)n_in; (void)out_size;
    const float* emb    = (const float*)d_in[0];
    const float* Win    = (const float*)d_in[1];
    const float* b_in   = (const float*)d_in[2];
    const float* phi    = (const float*)d_in[3];
    const float* Wout   = (const float*)d_in[4];
    const float* b_out  = (const float*)d_in[5];
    const float* phiq   = (const float*)d_in[6];
    const float* Whead  = (const float*)d_in[7];
    const float* b_head = (const float*)d_in[8];
    const int*   sent32 = (const int*)d_in[9];
    float* out = (float*)d_out;

    Angles A;
    build_angles(A);   // deterministic; recomputed every call (cheap)

    k_detect<<<1, 256>>>((const int4*)sent32, phiq);
    k_project<<<NROWS / 8, 256>>>(emb, Win, b_in, phi, sent32);
    k_recur<<<BATCH, 32>>>(Win, Wout, b_out);
    k_head<<<NROWS / 8, 256>>>(Whead, b_head, out, A);
}

// round 10
// speedup vs baseline: 2.5873x; 1.4527x over previous
#include <cuda_runtime.h>
#include <cstdint>
#include <math.h>

// Problem constants
#define S_LEN  128
#define BATCH  128
#define EDIM   64
#define HDIM   8
#define TDIM   12
#define NROWS  (S_LEN*BATCH)   // 16384
#define FULLM  0xffffffffu
#define NOPS   30
#define PROJ_ROWS 128

// -------------------- device scratch (no allocations allowed) ---------------
__device__ float g_Zx[NROWS * 32];    // per-(s,b) input projection (+b_in+phi), 2 MB
__device__ float g_hs[NROWS * HDIM];  // hidden states hs[s][b][h], 512 KB
__device__ int   g_flag;              // 1 => sentence buffer is int32, 0 => int64
__device__ float g_phiq_c[8], g_phiq_s[8];

// ============================================================================
// numpy-legacy MT19937 — constexpr so the circuit STRUCTURE is compile-time.
// ============================================================================
namespace mtrng {
struct MT { uint32_t key[624]; int pos; };
constexpr void mt_seed(MT& st, uint32_t s) {
    for (int i = 0; i < 624; i++) { st.key[i] = s; s = 1812433253u * (s ^ (s >> 30)) + (uint32_t)i + 1u; }
    st.pos = 624;
}
constexpr void mt_gen(MT& st) {
    int i = 0; uint32_t y = 0;
    for (i = 0; i < 624 - 397; i++) {
        y = (st.key[i] & 0x80000000u) | (st.key[i + 1] & 0x7fffffffu);
        st.key[i] = st.key[i + 397] ^ (y >> 1) ^ ((y & 1u) ? 0x9908b0dfu : 0u);
    }
    for (; i < 623; i++) {
        y = (st.key[i] & 0x80000000u) | (st.key[i + 1] & 0x7fffffffu);
        st.key[i] = st.key[i - 227] ^ (y >> 1) ^ ((y & 1u) ? 0x9908b0dfu : 0u);
    }
    y = (st.key[623] & 0x80000000u) | (st.key[0] & 0x7fffffffu);
    st.key[623] = st.key[396] ^ (y >> 1) ^ ((y & 1u) ? 0x9908b0dfu : 0u);
    st.pos = 0;
}
constexpr uint32_t mt_next(MT& st) {
    if (st.pos == 624) mt_gen(st);
    uint32_t y = st.key[st.pos++];
    y ^= y >> 11; y ^= (y << 7) & 0x9d2c5680u; y ^= (y << 15) & 0xefc60000u; y ^= y >> 18;
    return y;
}
constexpr int mt_randint(MT& st, uint32_t n) {
    uint32_t rng = n - 1u;
    uint32_t mask = rng;
    mask |= mask >> 1; mask |= mask >> 2; mask |= mask >> 4; mask |= mask >> 8; mask |= mask >> 16;
    uint32_t v = 0;
    do { v = mt_next(st) & mask; } while (v > rng);
    return (int)v;
}
constexpr double mt_double(MT& st) {
    uint32_t a = mt_next(st) >> 5, b = mt_next(st) >> 6;
    return ((double)a * 67108864.0 + (double)b) / 9007199254740992.0;
}
} // namespace mtrng

// Compile-time circuit structure
struct COps { int type[NOPS]; int pa[NOPS]; int pb[NOPS]; };
constexpr COps make_cops() {
    COps P{};
    mtrng::MT st{}; mtrng::mt_seed(st, 1234u);
    for (int i = 0; i < NOPS; i++) {
        int kind = mtrng::mt_randint(st, 4);
        if (kind == 3) {
            int c = mtrng::mt_randint(st, 8);
            int t = mtrng::mt_randint(st, 7);
            if (t >= c) t += 1;
            P.type[i] = 3; P.pa[i] = c; P.pb[i] = t;
        } else {
            int g = kind % 3;
            int w = mtrng::mt_randint(st, 8);
            (void)mtrng::mt_double(st);   // consume the angle draws
            P.type[i] = g; P.pa[i] = w; P.pb[i] = -1;
        }
    }
    return P;
}
constexpr COps COPS = make_cops();

// Runtime angle values (same MT walk; structure must match COPS)
struct Angles { float c[NOPS]; float s[NOPS]; };
static void build_angles(Angles& A) {
    mtrng::MT st; mtrng::mt_seed(st, 1234u);
    for (int i = 0; i < NOPS; i++) {
        int kind = mtrng::mt_randint(st, 4);
        if (kind == 3) {
            (void)mtrng::mt_randint(st, 8);
            (void)mtrng::mt_randint(st, 7);
            A.c[i] = 0.f; A.s[i] = 0.f;
        } else {
            (void)mtrng::mt_randint(st, 8);
            double ang = mtrng::mt_double(st) * (2.0 * M_PI);
            float th = (float)ang;            // reference casts to float32
            double half = (double)(th * 0.5f);
            A.c[i] = (float)cos(half); A.s[i] = (float)sin(half);
        }
    }
}

// ============================================================================
// Kernel A: detect sentence dtype + precompute phiq cos/sin
// ============================================================================
__global__ void k_detect(const int4* __restrict__ sent4, const float* __restrict__ phiq) {
    __shared__ int any;
    if (threadIdx.x == 0) any = 0;
    __syncthreads();
    int loc = 0;
    for (int i = threadIdx.x; i < 4096; i += blockDim.x) {
        int4 v = sent4[i];
        loc |= v.y | v.w;
    }
    if (loc) atomicOr(&any, 1);
    __syncthreads();
    if (threadIdx.x == 0) g_flag = any ? 1 : 0;
    if (threadIdx.x < 8) {
        float c, s;
        __sincosf(0.5f * phiq[threadIdx.x], &s, &c);
        g_phiq_c[threadIdx.x] = c;
        g_phiq_s[threadIdx.x] = s;
    }
}

// ============================================================================
// Kernel B: embed-gather + input projection as smem-tiled GEMM.
// out[16384,32] = gather(X)[16384,64] @ W^T + (b_in + phi)
// CTA = 128 rows; each thread computes a 4x4 register tile.
// ============================================================================
__global__ void __launch_bounds__(256) k_project(const float* __restrict__ emb,
                                                 const float* __restrict__ Win,
                                                 const float* __restrict__ b_in,
                                                 const float* __restrict__ phi,
                                                 const int*   __restrict__ sent32) {
    __shared__ __align__(16) float sX[PROJ_ROWS][65];  // pad 65: conflict-free
    __shared__ __align__(16) float sW[64][36];         // transposed W, float4-aligned rows
    __shared__ __align__(16) float sB[32];

    int tid  = threadIdx.x;
    int lane = tid & 31;
    int wid  = tid >> 5;
    int rowbase = blockIdx.x * PROJ_ROWS;
    int flag = g_flag;

    // ---- load W transposed: sW[k][o] = Win[o][k] (one-time; conflict-free STS) ----
#pragma unroll
    for (int j = 0; j < 8; j++) {
        int i = tid + j * 256;       // 0..2047
        int o = i & 31, k = i >> 5;
        sW[k][o] = Win[o * 72 + k];
    }
    if (tid < 32) sB[tid] = b_in[tid] + phi[tid];

    // ---- gather X tile: one warp per row, coalesced 64-float rows ----
    for (int r = wid; r < PROJ_ROWS; r += 8) {
        int rr = rowbase + r;
        int tok = sent32[flag ? rr : 2 * rr];
        const float* xr = emb + (long)tok * EDIM;
        sX[r][lane]      = xr[lane];
        sX[r][lane + 32] = xr[lane + 32];
    }
    __syncthreads();

    // ---- compute 4x4 tile per thread ----
    int c0 = (tid & 7) * 4;        // output column base
    int r0 = (tid >> 3) * 4;       // row base within tile
    float acc[4][4];
    {
        float4 bv = *reinterpret_cast<const float4*>(&sB[c0]);
#pragma unroll
        for (int i = 0; i < 4; i++) {
            acc[i][0] = bv.x; acc[i][1] = bv.y; acc[i][2] = bv.z; acc[i][3] = bv.w;
        }
    }

#pragma unroll 4
    for (int k = 0; k < 64; k++) {
        float4 w = *reinterpret_cast<const float4*>(&sW[k][c0]);   // 1 wavefront
        float x0 = sX[r0][k];        // 4 distinct banks, 8-way broadcast
        float x1 = sX[r0 + 1][k];
        float x2 = sX[r0 + 2][k];
        float x3 = sX[r0 + 3][k];
        acc[0][0] = fmaf(x0, w.x, acc[0][0]); acc[0][1] = fmaf(x0, w.y, acc[0][1]);
        acc[0][2] = fmaf(x0, w.z, acc[0][2]); acc[0][3] = fmaf(x0, w.w, acc[0][3]);
        acc[1][0] = fmaf(x1, w.x, acc[1][0]); acc[1][1] = fmaf(x1, w.y, acc[1][1]);
        acc[1][2] = fmaf(x1, w.z, acc[1][2]); acc[1][3] = fmaf(x1, w.w, acc[1][3]);
        acc[2][0] = fmaf(x2, w.x, acc[2][0]); acc[2][1] = fmaf(x2, w.y, acc[2][1]);
        acc[2][2] = fmaf(x2, w.z, acc[2][2]); acc[2][3] = fmaf(x2, w.w, acc[2][3]);
        acc[3][0] = fmaf(x3, w.x, acc[3][0]); acc[3][1] = fmaf(x3, w.y, acc[3][1]);
        acc[3][2] = fmaf(x3, w.z, acc[3][2]); acc[3][3] = fmaf(x3, w.w, acc[3][3]);
    }

#pragma unroll
    for (int i = 0; i < 4; i++) {
        float4 v = make_float4(acc[i][0], acc[i][1], acc[i][2], acc[i][3]);
        *reinterpret_cast<float4*>(&g_Zx[(rowbase + r0 + i) * 32 + c0]) = v;
    }
}

// ============================================================================
// Kernel C: sequential recurrence (one warp per batch element).
// Cross-lane communication via shared memory (LDS broadcast).
// ============================================================================
__device__ __forceinline__ float fast_tanh(float x) {
    float r; asm("tanh.approx.f32 %0, %1;" : "=f"(r) : "f"(x)); return r;
}

__global__ void __launch_bounds__(32, 1) k_recur(const float* __restrict__ Win,
                                                 const float* __restrict__ Wout,
                                                 const float* __restrict__ b_out) {
    __shared__ __align__(16) float sp[32];    // per-lane cos values
    __shared__ __align__(16) float sact[32];  // per-lane activations
    __shared__ __align__(16) float sh[8];     // hidden vector

    int b = blockIdx.x;
    int lane = threadIdx.x & 31;
    int g    = lane >> 3;
    int q    = lane & 7;
    int base = lane & 24;

    float Wh[8];
#pragma unroll
    for (int j = 0; j < 8; j++) Wh[j] = Win[lane * 72 + 64 + j];
    float Wo[8];
#pragma unroll
    for (int j = 0; j < 8; j++) Wo[j] = Wout[g * 64 + q * 8 + j];
    float bo = b_out[lane];

    // act = fma(aA, tanh(aB*pre), aC):
    //   sigmoid (g=0,1,3): 0.5 + 0.5*tanh(0.5*x);  tanh (g=2): tanh(x)
    float aAB = (g == 2) ? 1.f : 0.5f;
    float aC  = (g == 2) ? 0.f : 0.5f;

    float h[8];
#pragma unroll
    for (int j = 0; j < 8; j++) h[j] = 0.f;
    float cst = 0.f;

    const int BSTR = BATCH * 32;
    const float* Zp = g_Zx + b * 32 + lane;
    float zA = Zp[0];
    float zB = Zp[BSTR];

#pragma unroll 2
    for (int s = 0; s < S_LEN; s++) {
        // prefetch 2 steps ahead (covers L2 latency)
        float zC = (s + 2 < S_LEN) ? Zp[(s + 2) * BSTR] : 0.f;

        // z = zA + Wh·h   (two accumulator chains)
        float za = zA, zb = 0.f;
#pragma unroll
        for (int j = 0; j < 8; j += 2) {
            za = fmaf(Wh[j],     h[j],     za);
            zb = fmaf(Wh[j + 1], h[j + 1], zb);
        }
        float p = __cosf(za + zb);

        // ---- phase 1: share cos values via smem ----
        sp[lane] = p;
        __syncwarp();
        float4 pa = *reinterpret_cast<const float4*>(sp + base);
        float4 pb = *reinterpret_cast<const float4*>(sp + base + 4);

        // depth-3 prefix-product tree
        float t01 = pa.x * pa.y, t23 = pa.z * pa.w;
        float t45 = pb.x * pb.y, t67 = pb.z * pb.w;
        float q03 = t01 * t23;
        float P0 = pa.x;
        float P1 = t01;
        float P2 = t01 * pa.z;
        float P3 = q03;
        float P4 = q03 * pb.x;
        float P5 = q03 * t45;
        float P6 = P5 * pb.z;
        float P7 = q03 * (t45 * t67);

        // two-chain Wout dot
        float prA = fmaf(Wo[0], P0, bo);
        float prB = Wo[1] * P1;
        prA = fmaf(Wo[2], P2, prA);
        prB = fmaf(Wo[3], P3, prB);
        prA = fmaf(Wo[4], P4, prA);
        prB = fmaf(Wo[5], P5, prB);
        prA = fmaf(Wo[6], P6, prA);
        prB = fmaf(Wo[7], P7, prB);
        float pre = prA + prB;

        // activation via single MUFU.TANH
        float act = fmaf(aAB, fast_tanh(aAB * pre), aC);

        // ---- phase 2: share activations via smem ----
        sact[lane] = act;
        __syncwarp();
        float fv = sact[q];
        float iv = sact[8 + q];
        float gv = sact[16 + q];
        float ov = sact[24 + q];

        cst = fmaf(fv, cst, iv * gv);
        float hval = ov * fast_tanh(cst);

        // ---- phase 3: share hidden vector via smem ----
        if (lane < 8) {
            sh[lane] = hval;
            g_hs[(s * BATCH + b) * HDIM + lane] = hval;
        }
        __syncwarp();
        float4 h0 = *reinterpret_cast<const float4*>(sh);
        float4 h1 = *reinterpret_cast<const float4*>(sh + 4);
        h[0] = h0.x; h[1] = h0.y; h[2] = h0.z; h[3] = h0.w;
        h[4] = h1.x; h[5] = h1.y; h[6] = h1.z; h[7] = h1.w;

        zA = zB; zB = zC;
    }
}

// ============================================================================
// Kernel D: quantum head — compile-time-specialized circuit.
// 256 amps: lane holds amps m = lane*8 + k. wire w <-> bit (7-w).
// bits 7..3 = lane bits (wires 0..4), bits 2..0 = intra-lane (wires 5..7).
// ============================================================================
template<int BB, bool RX>
__device__ __forceinline__ void rot_lane_t(float* ar, float* ai, float c, float s, int lane) {
    constexpr int delta = 1 << (BB - 3);
    float sgn = ((lane >> (BB - 3)) & 1) ? s : -s;   // for RY
#pragma unroll
    for (int k = 0; k < 8; k++) {
        float pr = __shfl_xor_sync(FULLM, ar[k], delta);
        float pi = __shfl_xor_sync(FULLM, ai[k], delta);
        if (RX) {
            float nr = fmaf(s, pi, c * ar[k]);
            float ni = fmaf(-s, pr, c * ai[k]);
            ar[k] = nr; ai[k] = ni;
        } else {
            ar[k] = fmaf(sgn, pr, c * ar[k]);
            ai[k] = fmaf(sgn, pi, c * ai[k]);
        }
    }
}

template<int M, bool RX>
__device__ __forceinline__ void rot_intra_tt(float* ar, float* ai, float c, float s) {
#pragma unroll
    for (int k = 0; k < 8; k++) {
        if (!(k & M)) {
            const int k1 = k | M;
            float a0r = ar[k], a0i = ai[k], a1r = ar[k1], a1i = ai[k1];
            if (RX) {
                ar[k]  = fmaf(s, a1i, c * a0r);  ai[k]  = fmaf(-s, a1r, c * a0i);
                ar[k1] = fmaf(s, a0i, c * a1r);  ai[k1] = fmaf(-s, a0r, c * a1i);
            } else {
                ar[k]  = fmaf(-s, a1r, c * a0r); ai[k]  = fmaf(-s, a1i, c * a0i);
                ar[k1] = fmaf( s, a0r, c * a1r); ai[k1] = fmaf( s, a0i, c * a1i);
            }
        }
    }
}

template<int BB>
__device__ __forceinline__ void rz_t(float* ar, float* ai, float c, float s, int lane) {
    if (BB >= 3) {
        float sg = ((lane >> (BB - 3)) & 1) ? -s : s;
#pragma unroll
        for (int k = 0; k < 8; k++) {
            float nr = fmaf(sg, ai[k], c * ar[k]);
            float ni = fmaf(-sg, ar[k], c * ai[k]);
            ar[k] = nr; ai[k] = ni;
        }
    } else {
#pragma unroll
        for (int k = 0; k < 8; k++) {
            float sg = ((k >> BB) & 1) ? -s : s;   // compile-time fold per k
            float nr = fmaf(sg, ai[k], c * ar[k]);
            float ni = fmaf(-sg, ar[k], c * ai[k]);
            ar[k] = nr; ai[k] = ni;
        }
    }
}

template<int BC, int BT>
__device__ __forceinline__ void cnot_t(float* ar, float* ai, int lane) {
    if (BC >= 3 && BT >= 3) {
        constexpr int delta = (BT >= 3) ? (1 << (BT - 3)) : 1;
        int ctrl = (lane >> (BC - 3)) & 1;
#pragma unroll
        for (int k = 0; k < 8; k++) {
            float pr = __shfl_xor_sync(FULLM, ar[k], delta);
            float pi = __shfl_xor_sync(FULLM, ai[k], delta);
            if (ctrl) { ar[k] = pr; ai[k] = pi; }
        }
    } else if (BC >= 3) {
        constexpr int M = (BT < 3) ? (1 << BT) : 1;
        bool ctrl = ((lane >> (BC - 3)) & 1) != 0;
#pragma unroll
        for (int k = 0; k < 8; k++) if (!(k & M)) {
            const int k1 = k | M;
            float t0r = ctrl ? ar[k1] : ar[k];
            float t1r = ctrl ? ar[k]  : ar[k1];
            float t0i = ctrl ? ai[k1] : ai[k];
            float t1i = ctrl ? ai[k]  : ai[k1];
            ar[k] = t0r; ar[k1] = t1r; ai[k] = t0i; ai[k1] = t1i;
        }
    } else if (BT >= 3) {
        constexpr int delta = (BT >= 3) ? (1 << (BT - 3)) : 1;
        constexpr int MC = (BC < 3) ? (1 << BC) : 1;
#pragma unroll
        for (int k = 0; k < 8; k++) if (k & MC) {
            ar[k] = __shfl_xor_sync(FULLM, ar[k], delta);
            ai[k] = __shfl_xor_sync(FULLM, ai[k], delta);
        }
    } else {
        constexpr int MC = (BC < 3) ? (1 << BC) : 1;
        constexpr int M  = (BT < 3) ? (1 << BT) : 1;
#pragma unroll
        for (int k = 0; k < 8; k++) if ((k & MC) && !(k & M)) {
            const int k1 = k | M;
            float t = ar[k]; ar[k] = ar[k1]; ar[k1] = t;
            t = ai[k]; ai[k] = ai[k1]; ai[k1] = t;   // pure register rename
        }
    }
}

template<int I>
__device__ __forceinline__ void apply_ops(float* ar, float* ai,
                                          const float* Pc, const float* Ps, int lane) {
    if constexpr (I < NOPS) {
        constexpr int ty = COPS.type[I];
        if constexpr (ty == 3) {
            cnot_t<7 - COPS.pa[I], 7 - COPS.pb[I]>(ar, ai, lane);
        } else {
            constexpr int bb = 7 - COPS.pa[I];
            const float c = Pc[I], s = Ps[I];
            if constexpr (ty == 2)      rz_t<bb>(ar, ai, c, s, lane);
            else if constexpr (bb >= 3) rot_lane_t<bb, ty == 0>(ar, ai, c, s, lane);
            else                        rot_intra_tt<(1 << bb), ty == 0>(ar, ai, c, s);
        }
        apply_ops<I + 1>(ar, ai, Pc, Ps, lane);
    }
}

template<int W>
__device__ __forceinline__ void apply_phiq(float* ar, float* ai, int lane) {
    if constexpr (W < 8) {
        float c = g_phiq_c[W];
        float s = g_phiq_s[W];
        constexpr int BB = 7 - W;
        if constexpr (BB >= 3) rot_lane_t<BB, true>(ar, ai, c, s, lane);
        else                   rot_intra_tt<(1 << BB), true>(ar, ai, c, s);
        apply_phiq<W + 1>(ar, ai, lane);
    }
}

__global__ void __launch_bounds__(256) k_head(const float* __restrict__ Whead,
                                              const float* __restrict__ b_head,
                                              float* __restrict__ out,
                                              Angles A) {
    int warp = blockIdx.x * (blockDim.x >> 5) + (threadIdx.x >> 5);
    int lane = threadIdx.x & 31;
    if (warp >= NROWS) return;
    int r  = warp;
    int sp = r >> 7;        // s'
    int bp = r & 127;       // b'
    // out[s'][b'] <- hidden at (s = b', batch = s')   (batch-major reshape algebra)
    int hoff = ((bp << 7) + sp) * HDIM;

    // ---- encode: product state from RY angles ----
    float ce = 1.f, se = 0.f;
    if (lane < 8) {
        float th = 0.5f * g_hs[hoff + lane];
        __sincosf(th, &se, &ce);
    }
    float Fl = 1.f;
#pragma unroll
    for (int w = 0; w < 5; w++) {
        float cw = __shfl_sync(FULLM, ce, w);
        float sw = __shfl_sync(FULLM, se, w);
        Fl *= ((lane >> (4 - w)) & 1) ? sw : cw;
    }
    float c5 = __shfl_sync(FULLM, ce, 5), s5v = __shfl_sync(FULLM, se, 5);
    float c6 = __shfl_sync(FULLM, ce, 6), s6v = __shfl_sync(FULLM, se, 6);
    float c7 = __shfl_sync(FULLM, ce, 7), s7v = __shfl_sync(FULLM, se, 7);
    float ar[8], ai[8];
#pragma unroll
    for (int k = 0; k < 8; k++) {
        float f = ((k & 4) ? s5v : c5) * ((k & 2) ? s6v : c6) * ((k & 1) ? s7v : c7);
        ar[k] = Fl * f; ai[k] = 0.f;
    }

    // ---- fixed random layer (fully unrolled, compile-time structure) ----
    apply_ops<0>(ar, ai, A.c, A.s, lane);

    // ---- trainable RX(phiq) on every wire (precomputed cos/sin) ----
    apply_phiq<0>(ar, ai, lane);

    // ---- measure <Z_w> ----
    float p[8];
#pragma unroll
    for (int k = 0; k < 8; k++) p[k] = fmaf(ar[k], ar[k], ai[k] * ai[k]);
    float tot = 0.f, sA = 0.f, sB = 0.f, sC = 0.f;
#pragma unroll
    for (int k = 0; k < 8; k++) {
        tot += p[k];
        sA += (k & 4) ? -p[k] : p[k];
        sB += (k & 2) ? -p[k] : p[k];
        sC += (k & 1) ? -p[k] : p[k];
    }
    // FWHT over lanes: lane L ends with sum_j (-1)^{popc(L&j)} tot_j
    float x = tot;
#pragma unroll
    for (int d = 16; d >= 1; d >>= 1) {
        float o = __shfl_xor_sync(FULLM, x, d);
        x = (lane & d) ? (o - x) : (x + o);
    }
    float z[8];
    z[0] = __shfl_sync(FULLM, x, 16);
    z[1] = __shfl_sync(FULLM, x, 8);
    z[2] = __shfl_sync(FULLM, x, 4);
    z[3] = __shfl_sync(FULLM, x, 2);
    z[4] = __shfl_sync(FULLM, x, 1);
#pragma unroll
    for (int d = 16; d >= 1; d >>= 1) {
        sA += __shfl_xor_sync(FULLM, sA, d);
        sB += __shfl_xor_sync(FULLM, sB, d);
        sC += __shfl_xor_sync(FULLM, sC, d);
    }
    z[5] = sA; z[6] = sB; z[7] = sC;

    // ---- logits + log_softmax over T=12 ----
    float lg = 0.f;
    if (lane < TDIM) {
        lg = b_head[lane];
#pragma unroll
        for (int k = 0; k < 8; k++) lg = fmaf(z[k], Whead[lane * 8 + k], lg);
    }
    float mv = (lane < TDIM) ? lg : -3.0e38f;
#pragma unroll
    for (int d = 16; d >= 1; d >>= 1) mv = fmaxf(mv, __shfl_xor_sync(FULLM, mv, d));
    float ev = (lane < TDIM) ? __expf(lg - mv) : 0.f;
#pragma unroll
    for (int d = 16; d >= 1; d >>= 1) ev += __shfl_xor_sync(FULLM, ev, d);
    if (lane < TDIM) out[r * TDIM + lane] = lg - mv - __logf(ev);
}

// ============================================================================
// Launch
// ============================================================================
extern "C" void kernel_launch(void* const* d_in, const int* in_sizes, int n_in,
                              void* d_out, int out_size) {
    (void)in_sizes; (void)n_in; (void)out_size;
    const float* emb    = (const float*)d_in[0];
    const float* Win    = (const float*)d_in[1];
    const float* b_in   = (const float*)d_in[2];
    const float* phi    = (const float*)d_in[3];
    const float* Wout   = (const float*)d_in[4];
    const float* b_out  = (const float*)d_in[5];
    const float* phiq   = (const float*)d_in[6];
    const float* Whead  = (const float*)d_in[7];
    const float* b_head = (const float*)d_in[8];
    const int*   sent32 = (const int*)d_in[9];
    float* out = (float*)d_out;

    Angles A;
    build_angles(A);   // deterministic; recomputed every call (cheap)

    k_detect<<<1, 256>>>((const int4*)sent32, phiq);
    k_project<<<NROWS / PROJ_ROWS, 256>>>(emb, Win, b_in, phi, sent32);
    k_recur<<<BATCH, 32>>>(Win, Wout, b_out);
    k_head<<<NROWS / 8, 256>>>(Whead, b_head, out, A);
}